// round 2
// baseline (speedup 1.0000x reference)
#include <cuda_runtime.h>
#include <math.h>

// ---------------- problem constants ----------------
#define BB     8      // batch
#define NE     4      // n_equi
#define TT     1024   // T
#define DD     1024   // D_eq
#define GG     8      // N_GROUP
#define BL     128    // BLOCKS
#define SS     64     // T_text
#define DL     2048   // d_llm
#define SCALE  0.08838834764831843f   // 128^-0.5

#define TOK    16     // tokens per block in fused kernel

// ---------------- scratch (device globals; no allocs allowed) ----------------
__device__ float g_kp[16 * BB * SS * BL];   // split-K partials for k
__device__ float g_vp[16 * BB * SS * BL];   // split-K partials for v
__device__ float g_k [BB * SS * BL];
__device__ float g_v [BB * SS * BL];

// ================= kernel 1: k/v projection, split over d_llm =================
// grid (16 d-chunks, 8 b), 256 threads. smem: hs[64*128] + WkT/WvT[128*129]
#define K1_SMEM_F (8192 + 2 * 128 * 129)
__global__ __launch_bounds__(256, 1)
void kv_partial_kernel(const float* __restrict__ h_llm,
                       const float* __restrict__ Wk,
                       const float* __restrict__ Wv) {
    extern __shared__ float sm[];
    float* hs  = sm;               // [s][d]   64*128
    float* wkT = sm + 8192;        // [d][o]   stride 129
    float* wvT = wkT + 128 * 129;

    const int dc  = blockIdx.x;
    const int b   = blockIdx.y;
    const int tid = threadIdx.x;

    for (int idx = tid; idx < SS * 128; idx += 256) {
        int s = idx >> 7, d = idx & 127;
        hs[idx] = h_llm[(b * SS + s) * DL + dc * 128 + d];
    }
    for (int idx = tid; idx < BL * 128; idx += 256) {
        int o = idx >> 7, d = idx & 127;
        wkT[d * 129 + o] = Wk[o * DL + dc * 128 + d];
        wvT[d * 129 + o] = Wv[o * DL + dc * 128 + d];
    }
    __syncthreads();

    const int o = tid & 127, half = tid >> 7;
    for (int s = half; s < SS; s += 2) {
        float ak = 0.f, av = 0.f;
        const float* hrow = hs + s * 128;
#pragma unroll 8
        for (int d = 0; d < 128; d++) {
            float h = hrow[d];
            ak += h * wkT[d * 129 + o];
            av += h * wvT[d * 129 + o];
        }
        int oidx = ((dc * BB + b) * SS + s) * BL + o;
        g_kp[oidx] = ak;
        g_vp[oidx] = av;
    }
}

// ================= kernel 1b: reduce partials + bias =================
__global__ void kv_reduce_kernel(const float* __restrict__ bk,
                                 const float* __restrict__ bv) {
    int idx = blockIdx.x * 256 + threadIdx.x;   // 0 .. 65535
    int o = idx & 127;
    float sk = bk[o], sv = bv[o];
#pragma unroll
    for (int dc = 0; dc < 16; dc++) {
        sk += g_kp[dc * (BB * SS * BL) + idx];
        sv += g_vp[dc * (BB * SS * BL) + idx];
    }
    g_k[idx] = sk;
    g_v[idx] = sv;
}

// ================= kernel 2: fused per-token-tile kernel =================
// grid (T/16, n_equi, B), 256 threads, 1 CTA/SM (224000 B dyn smem).
// smem float offsets:
#define OF_H   0                         // [m][d] stride 1028  : 16*1028 = 16448
#define OF_W   16448                     // [i][o] stride 132   : 128*132 = 16896
#define OF_KV  (16448 + 16896)           // kT[d][s] stride 65 (8320) + v[s][d] (8192); later hT[i][r] (16384)
#define OF_A   (OF_KV + 16512)           // AT[i or d][m] stride 16 : 2048  (inv -> ctx)
#define OF_Q   (OF_A + 2048)             // [m][o] : 2048  (q -> gamma)
#define OF_U   (OF_Q + 2048)             // scores [m][68] -> beta [m][o] : 2048
#define K2_SMEM_F (OF_U + 2048)          // 56000 floats = 224000 bytes

__global__ __launch_bounds__(256, 1)
void fused_kernel(const float* __restrict__ h_prime,
                  const float* __restrict__ Wq, const float* __restrict__ bq,
                  const float* __restrict__ Wg, const float* __restrict__ bg,
                  const float* __restrict__ Wb, const float* __restrict__ bb,
                  const float* __restrict__ We,
                  float* __restrict__ out) {
    extern __shared__ float sm[];
    float* H  = sm + OF_H;
    float* W  = sm + OF_W;
    float* KV = sm + OF_KV;
    float* kT = KV;                 // [d*65 + s]
    float* v  = KV + 8320;          // [s*128 + d]
    float* hT = KV;                 // [i*128 + (g*16+m)]  (after ctx)
    float* AT = sm + OF_A;          // [k*16 + m]
    float* Q  = sm + OF_Q;          // [m*128 + o]
    float* U  = sm + OF_U;

    const int tid = threadIdx.x;
    const int t0  = blockIdx.x * TOK;
    const int n   = blockIdx.y;
    const int b   = blockIdx.z;
    const long long base = ((long long)(b * NE + n) * TT + t0) * DD;

    // ---- phase A: loads ----
    // h_prime tile -> H (stride 1028), float4
    for (int j = tid; j < TOK * DD / 4; j += 256) {
        int e = j * 4;
        int m = e >> 10, d = e & 1023;
        float4 val = *reinterpret_cast<const float4*>(h_prime + base + m * DD + d);
        *reinterpret_cast<float4*>(&H[m * 1028 + d]) = val;
    }
    // k transposed, v direct
    for (int idx = tid; idx < SS * BL; idx += 256) {
        int s = idx >> 7, d = idx & 127;
        kT[d * 65 + s] = g_k[(b * SS + s) * BL + d];
        v[idx]         = g_v[b * SS * BL + idx];
    }
    // Wq transposed -> W
    for (int idx = tid; idx < BL * BL; idx += 256) {
        int o = idx >> 7, i = idx & 127;
        W[i * 132 + o] = Wq[idx];
    }
    __syncthreads();

    // ---- phase B: inv_feat (group max) -> AT[i][m] ----
    for (int idx = tid; idx < BL * TOK; idx += 256) {
        int i = idx >> 4, m = idx & 15;
        float mx = -1e30f;
#pragma unroll
        for (int g = 0; g < GG; g++)
            mx = fmaxf(mx, H[m * 1028 + g * 128 + i]);
        AT[idx] = mx;
    }
    __syncthreads();

    // ---- phase C: q = inv @ WqT + bq  -> Q[m][o] ----
    {
        const int o = tid & 127, mh = tid >> 7;   // mh in {0,1}, m = mh*8 + j
        float acc[8];
        float bias = bq[o];
#pragma unroll
        for (int j = 0; j < 8; j++) acc[j] = bias;
#pragma unroll 4
        for (int i = 0; i < 128; i++) {
            float wv = W[i * 132 + o];
            float4 a0 = *reinterpret_cast<const float4*>(&AT[i * 16 + mh * 8]);
            float4 a1 = *reinterpret_cast<const float4*>(&AT[i * 16 + mh * 8 + 4]);
            acc[0] += a0.x * wv; acc[1] += a0.y * wv;
            acc[2] += a0.z * wv; acc[3] += a0.w * wv;
            acc[4] += a1.x * wv; acc[5] += a1.y * wv;
            acc[6] += a1.z * wv; acc[7] += a1.w * wv;
        }
#pragma unroll
        for (int j = 0; j < 8; j++) Q[(mh * 8 + j) * 128 + o] = acc[j];
    }
    __syncthreads();

    // ---- phase D: scores = q . k * SCALE -> U[m][68] ----
    {
        const int s = tid & 63, mq = tid >> 6;
        for (int m = mq; m < TOK; m += 4) {
            float acc = 0.f;
#pragma unroll 8
            for (int d = 0; d < 128; d += 4) {
                float4 qv = *reinterpret_cast<const float4*>(&Q[m * 128 + d]);
                acc += qv.x * kT[(d + 0) * 65 + s];
                acc += qv.y * kT[(d + 1) * 65 + s];
                acc += qv.z * kT[(d + 2) * 65 + s];
                acc += qv.w * kT[(d + 3) * 65 + s];
            }
            U[m * 68 + s] = acc * SCALE;
        }
    }
    __syncthreads();

    // ---- phase E: softmax per row (16 threads) ----
    if (tid < TOK) {
        float* row = U + tid * 68;
        float mx = row[0];
#pragma unroll 8
        for (int s = 1; s < SS; s++) mx = fmaxf(mx, row[s]);
        float sum = 0.f;
#pragma unroll 8
        for (int s = 0; s < SS; s++) { float e = expf(row[s] - mx); row[s] = e; sum += e; }
        float inv = 1.f / sum;
#pragma unroll 8
        for (int s = 0; s < SS; s++) row[s] *= inv;
    }
    __syncthreads();

    // ---- phase F: ctx = attn @ v -> AT[d][m] ----
    {
        const int m = tid & 15, dh = tid >> 4;   // dh 0..15, 8 d each
        for (int dd = 0; dd < 8; dd++) {
            int d = dh * 8 + dd;
            float acc = 0.f;
#pragma unroll 8
            for (int s = 0; s < SS; s += 4) {
                float4 uv = *reinterpret_cast<const float4*>(&U[m * 68 + s]);
                acc += uv.x * v[(s + 0) * 128 + d];
                acc += uv.y * v[(s + 1) * 128 + d];
                acc += uv.z * v[(s + 2) * 128 + d];
                acc += uv.w * v[(s + 3) * 128 + d];
            }
            AT[d * 16 + m] = acc;
        }
    }
    __syncthreads();

    // ---- phase G: gamma = ctx @ WgT + bg -> Q[m][o] ----
    for (int idx = tid; idx < BL * BL; idx += 256) {   // load Wg transposed
        int o = idx >> 7, i = idx & 127;
        W[i * 132 + o] = Wg[idx];
    }
    __syncthreads();
    {
        const int o = tid & 127, mh = tid >> 7;
        float acc[8];
        float bias = bg[o];
#pragma unroll
        for (int j = 0; j < 8; j++) acc[j] = bias;
#pragma unroll 4
        for (int i = 0; i < 128; i++) {
            float wv = W[i * 132 + o];
            float4 a0 = *reinterpret_cast<const float4*>(&AT[i * 16 + mh * 8]);
            float4 a1 = *reinterpret_cast<const float4*>(&AT[i * 16 + mh * 8 + 4]);
            acc[0] += a0.x * wv; acc[1] += a0.y * wv;
            acc[2] += a0.z * wv; acc[3] += a0.w * wv;
            acc[4] += a1.x * wv; acc[5] += a1.y * wv;
            acc[6] += a1.z * wv; acc[7] += a1.w * wv;
        }
#pragma unroll
        for (int j = 0; j < 8; j++) Q[(mh * 8 + j) * 128 + o] = acc[j];
    }
    __syncthreads();

    // ---- phase H: beta = ctx @ WbT + bb -> U[m][o] ----
    for (int idx = tid; idx < BL * BL; idx += 256) {
        int o = idx >> 7, i = idx & 127;
        W[i * 132 + o] = Wb[idx];
    }
    __syncthreads();
    {
        const int o = tid & 127, mh = tid >> 7;
        float acc[8];
        float bias = bb[o];
#pragma unroll
        for (int j = 0; j < 8; j++) acc[j] = bias;
#pragma unroll 4
        for (int i = 0; i < 128; i++) {
            float wv = W[i * 132 + o];
            float4 a0 = *reinterpret_cast<const float4*>(&AT[i * 16 + mh * 8]);
            float4 a1 = *reinterpret_cast<const float4*>(&AT[i * 16 + mh * 8 + 4]);
            acc[0] += a0.x * wv; acc[1] += a0.y * wv;
            acc[2] += a0.z * wv; acc[3] += a0.w * wv;
            acc[4] += a1.x * wv; acc[5] += a1.y * wv;
            acc[6] += a1.z * wv; acc[7] += a1.w * wv;
        }
#pragma unroll
        for (int j = 0; j < 8; j++) U[(mh * 8 + j) * 128 + o] = acc[j];
    }
    __syncthreads();

    // ---- phase I: load We -> W ; build hT (k/v region is dead) ----
    for (int idx = tid; idx < BL * BL; idx += 256) {
        int o = idx >> 7, i = idx & 127;
        W[i * 132 + o] = We[idx];
    }
    for (int idx = tid; idx < BL * BL; idx += 256) {
        int i = idx >> 7, rr = idx & 127;
        int g = rr >> 4, m = rr & 15;
        hT[idx] = H[m * 1028 + g * 128 + i];   // row index r = g*16+m
    }
    __syncthreads();

    // ---- phase J: equi GEMM + modulation + residual + store ----
    {
        const int w  = tid >> 5;    // warp id == group g
        const int l  = tid & 31;
        const int ro = l >> 3;      // 0..3 -> m0 = ro*4
        const int oc = l & 7;       // 0..7
        const int g  = w;
        const int m0 = ro * 4;
        const int r0 = g * 16 + m0;

        for (int ot = 0; ot < 4; ot++) {
            const int o = ot * 32 + oc * 4;
            float acc[4][4];
#pragma unroll
            for (int a = 0; a < 4; a++)
#pragma unroll
                for (int c = 0; c < 4; c++) acc[a][c] = 0.f;

#pragma unroll 4
            for (int i = 0; i < 128; i++) {
                float4 wv = *reinterpret_cast<const float4*>(&W[i * 132 + o]);
                float4 hv = *reinterpret_cast<const float4*>(&hT[i * 128 + r0]);
                acc[0][0] += hv.x * wv.x; acc[0][1] += hv.x * wv.y;
                acc[0][2] += hv.x * wv.z; acc[0][3] += hv.x * wv.w;
                acc[1][0] += hv.y * wv.x; acc[1][1] += hv.y * wv.y;
                acc[1][2] += hv.y * wv.z; acc[1][3] += hv.y * wv.w;
                acc[2][0] += hv.z * wv.x; acc[2][1] += hv.z * wv.y;
                acc[2][2] += hv.z * wv.z; acc[2][3] += hv.z * wv.w;
                acc[3][0] += hv.w * wv.x; acc[3][1] += hv.w * wv.y;
                acc[3][2] += hv.w * wv.z; acc[3][3] += hv.w * wv.w;
            }

#pragma unroll
            for (int a = 0; a < 4; a++) {
                const int m = m0 + a;
                float4 gam = *reinterpret_cast<const float4*>(&Q[m * 128 + o]);
                float4 bet = *reinterpret_cast<const float4*>(&U[m * 128 + o]);
                float4 res = *reinterpret_cast<const float4*>(&H[m * 1028 + g * 128 + o]);
                float c0 = AT[(o + 0) * 16 + m];
                float c1 = AT[(o + 1) * 16 + m];
                float c2 = AT[(o + 2) * 16 + m];
                float c3 = AT[(o + 3) * 16 + m];
                float g0 = 1.f / (1.f + __expf(-c0));
                float g1 = 1.f / (1.f + __expf(-c1));
                float g2 = 1.f / (1.f + __expf(-c2));
                float g3 = 1.f / (1.f + __expf(-c3));
                float4 ov;
                ov.x = res.x + g0 * (gam.x * acc[a][0] + bet.x);
                ov.y = res.y + g1 * (gam.y * acc[a][1] + bet.y);
                ov.z = res.z + g2 * (gam.z * acc[a][2] + bet.z);
                ov.w = res.w + g3 * (gam.w * acc[a][3] + bet.w);
                *reinterpret_cast<float4*>(out + base + m * DD + g * 128 + o) = ov;
            }
        }
    }
}

// ================= launcher =================
extern "C" void kernel_launch(void* const* d_in, const int* in_sizes, int n_in,
                              void* d_out, int out_size) {
    const float* h_prime = (const float*)d_in[0];
    const float* h_llm   = (const float*)d_in[1];
    const float* Wq = (const float*)d_in[2];
    const float* bq = (const float*)d_in[3];
    const float* Wk = (const float*)d_in[4];
    const float* bk = (const float*)d_in[5];
    const float* Wv = (const float*)d_in[6];
    const float* bv = (const float*)d_in[7];
    const float* Wg = (const float*)d_in[8];
    const float* bg = (const float*)d_in[9];
    const float* Wb = (const float*)d_in[10];
    const float* bb = (const float*)d_in[11];
    const float* We = (const float*)d_in[12];
    float* out = (float*)d_out;

    (void)in_sizes; (void)n_in; (void)out_size;

    size_t sm1 = K1_SMEM_F * sizeof(float);
    size_t sm2 = K2_SMEM_F * sizeof(float);
    cudaFuncSetAttribute(kv_partial_kernel,
                         cudaFuncAttributeMaxDynamicSharedMemorySize, (int)sm1);
    cudaFuncSetAttribute(fused_kernel,
                         cudaFuncAttributeMaxDynamicSharedMemorySize, (int)sm2);

    kv_partial_kernel<<<dim3(16, BB), 256, sm1>>>(h_llm, Wk, Wv);
    kv_reduce_kernel<<<(BB * SS * BL) / 256, 256>>>(bk, bv);
    fused_kernel<<<dim3(TT / TOK, NE, BB), 256, sm2>>>(
        h_prime, Wq, bq, Wg, bg, Wb, bb, We, out);
}

// round 4
// speedup vs baseline: 1.4605x; 1.4605x over previous
#include <cuda_runtime.h>
#include <math.h>

// ---------------- problem constants ----------------
#define BB     8      // batch
#define NE     4      // n_equi
#define TT     1024   // T
#define DD     1024   // D_eq
#define GG     8      // N_GROUP
#define BL     128    // BLOCKS
#define SS     64     // T_text
#define DL     2048   // d_llm
#define SCALE  0.08838834764831843f   // 128^-0.5

#define TOK    16     // tokens per block in fused kernel

// ---------------- scratch (device globals; no allocs allowed) ----------------
__device__ float g_kp[16 * BB * SS * BL];
__device__ float g_vp[16 * BB * SS * BL];
__device__ float g_k [BB * SS * BL];
__device__ float g_v [BB * SS * BL];

// ================= kernel 1: k/v projection, split over d_llm =================
// grid (16 d-chunks, 8 b), 512 threads.
#define K1_SMEM_F (8192 + 2 * 128 * 129)
__global__ __launch_bounds__(512, 1)
void kv_partial_kernel(const float* __restrict__ h_llm,
                       const float* __restrict__ Wk,
                       const float* __restrict__ Wv) {
    extern __shared__ float sm[];
    float* hs  = sm;               // [s][d]  64*128
    float* wkT = sm + 8192;        // [d][o]  stride 129
    float* wvT = wkT + 128 * 129;

    const int dc  = blockIdx.x;
    const int b   = blockIdx.y;
    const int tid = threadIdx.x;

    // h slice: coalesced float4
    for (int e = tid; e < SS * 32; e += 512) {          // 2048 float4
        int s = e >> 5, d4 = e & 31;
        *reinterpret_cast<float4*>(&hs[s * 128 + d4 * 4]) =
            *reinterpret_cast<const float4*>(&h_llm[(b * SS + s) * DL + dc * 128 + d4 * 4]);
    }
    // weights transposed: read float4 over d, scatter scalars
    for (int e = tid; e < BL * 32; e += 512) {          // 4096 float4
        int d4 = e & 31, o = e >> 5;
        float4 wk = *reinterpret_cast<const float4*>(&Wk[o * DL + dc * 128 + d4 * 4]);
        float4 wv = *reinterpret_cast<const float4*>(&Wv[o * DL + dc * 128 + d4 * 4]);
        int d0 = d4 * 4;
        wkT[(d0 + 0) * 129 + o] = wk.x; wkT[(d0 + 1) * 129 + o] = wk.y;
        wkT[(d0 + 2) * 129 + o] = wk.z; wkT[(d0 + 3) * 129 + o] = wk.w;
        wvT[(d0 + 0) * 129 + o] = wv.x; wvT[(d0 + 1) * 129 + o] = wv.y;
        wvT[(d0 + 2) * 129 + o] = wv.z; wvT[(d0 + 3) * 129 + o] = wv.w;
    }
    __syncthreads();

    const int o = tid & 127, qi = tid >> 7;             // qi 0..3
    for (int st = 0; st < 4; st++) {
        int s0 = qi * 16 + st * 4;
        float ak[4] = {0.f, 0.f, 0.f, 0.f};
        float av[4] = {0.f, 0.f, 0.f, 0.f};
#pragma unroll 4
        for (int d = 0; d < 128; d++) {
            float wk = wkT[d * 129 + o];
            float wv = wvT[d * 129 + o];
#pragma unroll
            for (int j = 0; j < 4; j++) {
                float h = hs[(s0 + j) * 128 + d];       // broadcast
                ak[j] = fmaf(h, wk, ak[j]);
                av[j] = fmaf(h, wv, av[j]);
            }
        }
#pragma unroll
        for (int j = 0; j < 4; j++) {
            int oidx = ((dc * BB + b) * SS + s0 + j) * BL + o;
            g_kp[oidx] = ak[j];
            g_vp[oidx] = av[j];
        }
    }
}

// ================= kernel 1b: reduce partials + bias =================
__global__ void kv_reduce_kernel(const float* __restrict__ bk,
                                 const float* __restrict__ bv) {
    int idx = blockIdx.x * 256 + threadIdx.x;
    int o = idx & 127;
    float sk = bk[o], sv = bv[o];
#pragma unroll
    for (int dc = 0; dc < 16; dc++) {
        sk += g_kp[dc * (BB * SS * BL) + idx];
        sv += g_vp[dc * (BB * SS * BL) + idx];
    }
    g_k[idx] = sk;
    g_v[idx] = sv;
}

// ================= kernel 2: fused per-token-tile kernel =================
// grid (T/16, n_equi, B), 512 threads, 1 CTA/SM.
// smem float offsets:
#define OF_HT  0                          // hT[i][r] stride 132 : 128*132 = 16896
#define OF_WT  16896                      // WT[i][o] stride 132 : 16896
#define OF_K   (OF_WT + 16896)            // k[s][d] : 8192
#define OF_V   (OF_K + 8192)              // v[s][d] : 8192
#define OF_AT  (OF_V + 8192)              // AT[i][m] stride 16 : 2048 (inv -> ctx)
#define OF_Q   (OF_AT + 2048)             // Q[m][o] stride 132 : 2112 (q -> gamma)
#define OF_U   (OF_Q + 2112)              // U[m][*] stride 132 : 2112 (scores -> beta)
#define K2_SMEM_F (OF_U + 2112)           // 56448 floats = 225792 bytes

__device__ __forceinline__ void stage_weight_T(const float* __restrict__ Wsrc,
                                               float* __restrict__ WT, int tid) {
    // e bits: [2:0]=olow [4:3]=i4l [8:5]=ohi [11:9]=i4h  (4096 float4 total)
#pragma unroll
    for (int k = 0; k < 8; k++) {
        int e = tid + k * 512;
        int olow = e & 7, i4l = (e >> 3) & 3, ohi = (e >> 5) & 15, i4h = e >> 9;
        int o  = ohi * 8 + olow;
        int i0 = (i4h * 4 + i4l) * 4;
        float4 w = *reinterpret_cast<const float4*>(&Wsrc[o * 128 + i0]);
        WT[(i0 + 0) * 132 + o] = w.x;
        WT[(i0 + 1) * 132 + o] = w.y;
        WT[(i0 + 2) * 132 + o] = w.z;
        WT[(i0 + 3) * 132 + o] = w.w;
    }
}

__global__ __launch_bounds__(512, 1)
void fused_kernel(const float* __restrict__ h_prime,
                  const float* __restrict__ Wq, const float* __restrict__ bq,
                  const float* __restrict__ Wg, const float* __restrict__ bg,
                  const float* __restrict__ Wb, const float* __restrict__ bb,
                  const float* __restrict__ We,
                  float* __restrict__ out) {
    extern __shared__ float sm[];
    float* hT  = sm + OF_HT;   // [i*132 + g*16+m]
    float* WT  = sm + OF_WT;   // [i*132 + o]
    float* ksm = sm + OF_K;    // [s*128 + d]
    float* vsm = sm + OF_V;    // [s*128 + d]
    float* AT  = sm + OF_AT;   // [k*16 + m]
    float* Q   = sm + OF_Q;    // [m*132 + o]
    float* U   = sm + OF_U;    // [m*132 + *]

    const int tid = threadIdx.x;
    const int t0  = blockIdx.x * TOK;
    const int n   = blockIdx.y;
    const int b   = blockIdx.z;
    const long long base = ((long long)(b * NE + n) * TT + t0) * DD;

    // ---- phase A: loads ----
    // h tile, transposed on the fly (lanes vary m -> conflict-free stores)
#pragma unroll
    for (int k = 0; k < 8; k++) {
        int e = tid + k * 512;                 // 4096 float4
        int m = e & 15, d4 = e >> 4;
        int d = d4 * 4, g = d >> 7, i0 = d & 127;
        float4 hv = *reinterpret_cast<const float4*>(&h_prime[base + m * DD + d]);
        int r = g * 16 + m;
        hT[(i0 + 0) * 132 + r] = hv.x;
        hT[(i0 + 1) * 132 + r] = hv.y;
        hT[(i0 + 2) * 132 + r] = hv.z;
        hT[(i0 + 3) * 132 + r] = hv.w;
    }
    // k/v natural [s][d]
#pragma unroll
    for (int k = 0; k < 4; k++) {
        int e = tid + k * 512;                 // 2048 float4
        int s = e >> 5, d4 = e & 31;
        *reinterpret_cast<float4*>(&ksm[s * 128 + d4 * 4]) =
            *reinterpret_cast<const float4*>(&g_k[(b * SS + s) * BL + d4 * 4]);
        *reinterpret_cast<float4*>(&vsm[s * 128 + d4 * 4]) =
            *reinterpret_cast<const float4*>(&g_v[(b * SS + s) * BL + d4 * 4]);
    }
    stage_weight_T(Wq, WT, tid);
    __syncthreads();

    // ---- phase B: group max -> AT[i][m] ----
#pragma unroll
    for (int k = 0; k < 4; k++) {
        int idx = tid + k * 512;               // 2048
        int i = idx >> 4, m = idx & 15;
        const float* row = &hT[i * 132 + m];
        float mx = row[0];
#pragma unroll
        for (int g = 1; g < GG; g++) mx = fmaxf(mx, row[g * 16]);
        AT[i * 16 + m] = mx;
    }
    __syncthreads();

    // ---- phase C: q = inv @ WqT + bq -> Q[m][o] ----
    {
        const int o = tid & 127, mq = tid >> 7;
        float bias = bq[o];
        float acc[4] = {bias, bias, bias, bias};
#pragma unroll 8
        for (int i = 0; i < 128; i++) {
            float w = WT[i * 132 + o];
            float4 a4 = *reinterpret_cast<const float4*>(&AT[i * 16 + mq * 4]);
            acc[0] = fmaf(w, a4.x, acc[0]);
            acc[1] = fmaf(w, a4.y, acc[1]);
            acc[2] = fmaf(w, a4.z, acc[2]);
            acc[3] = fmaf(w, a4.w, acc[3]);
        }
#pragma unroll
        for (int j = 0; j < 4; j++) Q[(mq * 4 + j) * 132 + o] = acc[j];
    }
    __syncthreads();

    // ---- phase D: scores -> U[m][s] ; stage Wg (WT free) ----
    stage_weight_T(Wg, WT, tid);
    {
        const int m = tid & 15, sh = tid >> 4;  // sh 0..31
        float a0 = 0.f, a1 = 0.f;
#pragma unroll 8
        for (int d4 = 0; d4 < 32; d4++) {
            float4 q4 = *reinterpret_cast<const float4*>(&Q[m * 132 + d4 * 4]);
            float4 ka = *reinterpret_cast<const float4*>(&ksm[sh * 128 + d4 * 4]);
            float4 kb = *reinterpret_cast<const float4*>(&ksm[(sh + 32) * 128 + d4 * 4]);
            a0 = fmaf(q4.x, ka.x, a0); a0 = fmaf(q4.y, ka.y, a0);
            a0 = fmaf(q4.z, ka.z, a0); a0 = fmaf(q4.w, ka.w, a0);
            a1 = fmaf(q4.x, kb.x, a1); a1 = fmaf(q4.y, kb.y, a1);
            a1 = fmaf(q4.z, kb.z, a1); a1 = fmaf(q4.w, kb.w, a1);
        }
        U[m * 132 + sh]      = a0 * SCALE;
        U[m * 132 + sh + 32] = a1 * SCALE;
    }
    __syncthreads();

    // ---- phase E: softmax, one warp per row ----
    {
        const int w = tid >> 5, l = tid & 31;   // w = m (16 warps)
        float x0 = U[w * 132 + l];
        float x1 = U[w * 132 + l + 32];
        float mx = fmaxf(x0, x1);
#pragma unroll
        for (int off = 16; off > 0; off >>= 1)
            mx = fmaxf(mx, __shfl_xor_sync(0xffffffffu, mx, off));
        float e0 = __expf(x0 - mx), e1 = __expf(x1 - mx);
        float s = e0 + e1;
#pragma unroll
        for (int off = 16; off > 0; off >>= 1)
            s += __shfl_xor_sync(0xffffffffu, s, off);
        float inv = 1.f / s;
        U[w * 132 + l]      = e0 * inv;
        U[w * 132 + l + 32] = e1 * inv;
    }
    __syncthreads();

    // ---- phase F: ctx = attn @ v -> AT[d][m] ----
    {
        const int m = tid & 15, dh = tid >> 4;  // dh 0..31
        const int d0 = dh * 4;
        float acc[4] = {0.f, 0.f, 0.f, 0.f};
#pragma unroll 8
        for (int s = 0; s < SS; s++) {
            float u = U[m * 132 + s];
            float4 v4 = *reinterpret_cast<const float4*>(&vsm[s * 128 + d0]);
            acc[0] = fmaf(u, v4.x, acc[0]);
            acc[1] = fmaf(u, v4.y, acc[1]);
            acc[2] = fmaf(u, v4.z, acc[2]);
            acc[3] = fmaf(u, v4.w, acc[3]);
        }
#pragma unroll
        for (int j = 0; j < 4; j++) AT[(d0 + j) * 16 + m] = acc[j];
    }
    __syncthreads();

    // ---- phase G: gamma = ctx @ WgT + bg -> Q ----
    {
        const int o = tid & 127, mq = tid >> 7;
        float bias = bg[o];
        float acc[4] = {bias, bias, bias, bias};
#pragma unroll 8
        for (int i = 0; i < 128; i++) {
            float w = WT[i * 132 + o];
            float4 a4 = *reinterpret_cast<const float4*>(&AT[i * 16 + mq * 4]);
            acc[0] = fmaf(w, a4.x, acc[0]);
            acc[1] = fmaf(w, a4.y, acc[1]);
            acc[2] = fmaf(w, a4.z, acc[2]);
            acc[3] = fmaf(w, a4.w, acc[3]);
        }
#pragma unroll
        for (int j = 0; j < 4; j++) Q[(mq * 4 + j) * 132 + o] = acc[j];
    }
    __syncthreads();

    stage_weight_T(Wb, WT, tid);
    __syncthreads();

    // ---- phase H: beta = ctx @ WbT + bb -> U ----
    {
        const int o = tid & 127, mq = tid >> 7;
        float bias = bb[o];
        float acc[4] = {bias, bias, bias, bias};
#pragma unroll 8
        for (int i = 0; i < 128; i++) {
            float w = WT[i * 132 + o];
            float4 a4 = *reinterpret_cast<const float4*>(&AT[i * 16 + mq * 4]);
            acc[0] = fmaf(w, a4.x, acc[0]);
            acc[1] = fmaf(w, a4.y, acc[1]);
            acc[2] = fmaf(w, a4.z, acc[2]);
            acc[3] = fmaf(w, a4.w, acc[3]);
        }
#pragma unroll
        for (int j = 0; j < 4; j++) U[(mq * 4 + j) * 132 + o] = acc[j];
    }
    __syncthreads();

    stage_weight_T(We, WT, tid);
    __syncthreads();

    // ---- phase J: equi GEMM (8 rows x 4 cols per thread) + epilogue ----
    {
        const int w = tid >> 5, l = tid & 31;
        const int g = w >> 1, ohalf = w & 1;
        const int rt = l >> 4, ct = l & 15;
        const int o0 = ohalf * 64 + ct * 4;
        const int r0 = g * 16 + rt * 8;

        float acc[8][4];
#pragma unroll
        for (int a = 0; a < 8; a++)
#pragma unroll
            for (int c = 0; c < 4; c++) acc[a][c] = 0.f;

#pragma unroll 4
        for (int i = 0; i < 128; i++) {
            float4 h0 = *reinterpret_cast<const float4*>(&hT[i * 132 + r0]);
            float4 h1 = *reinterpret_cast<const float4*>(&hT[i * 132 + r0 + 4]);
            float4 w4 = *reinterpret_cast<const float4*>(&WT[i * 132 + o0]);
            float hv[8] = {h0.x, h0.y, h0.z, h0.w, h1.x, h1.y, h1.z, h1.w};
#pragma unroll
            for (int a = 0; a < 8; a++) {
                acc[a][0] = fmaf(hv[a], w4.x, acc[a][0]);
                acc[a][1] = fmaf(hv[a], w4.y, acc[a][1]);
                acc[a][2] = fmaf(hv[a], w4.z, acc[a][2]);
                acc[a][3] = fmaf(hv[a], w4.w, acc[a][3]);
            }
        }

#pragma unroll
        for (int a = 0; a < 8; a++) {
            const int m = rt * 8 + a;
            const int r = g * 16 + m;
            float4 gam = *reinterpret_cast<const float4*>(&Q[m * 132 + o0]);
            float4 bet = *reinterpret_cast<const float4*>(&U[m * 132 + o0]);
            float c0 = AT[(o0 + 0) * 16 + m];
            float c1 = AT[(o0 + 1) * 16 + m];
            float c2 = AT[(o0 + 2) * 16 + m];
            float c3 = AT[(o0 + 3) * 16 + m];
            float g0 = 1.f / (1.f + __expf(-c0));
            float g1 = 1.f / (1.f + __expf(-c1));
            float g2 = 1.f / (1.f + __expf(-c2));
            float g3 = 1.f / (1.f + __expf(-c3));
            float r0v = hT[(o0 + 0) * 132 + r];
            float r1v = hT[(o0 + 1) * 132 + r];
            float r2v = hT[(o0 + 2) * 132 + r];
            float r3v = hT[(o0 + 3) * 132 + r];
            float4 ov;
            ov.x = r0v + g0 * (gam.x * acc[a][0] + bet.x);
            ov.y = r1v + g1 * (gam.y * acc[a][1] + bet.y);
            ov.z = r2v + g2 * (gam.z * acc[a][2] + bet.z);
            ov.w = r3v + g3 * (gam.w * acc[a][3] + bet.w);
            *reinterpret_cast<float4*>(&out[base + m * DD + g * 128 + o0]) = ov;
        }
    }
}

// ================= launcher =================
extern "C" void kernel_launch(void* const* d_in, const int* in_sizes, int n_in,
                              void* d_out, int out_size) {
    const float* h_prime = (const float*)d_in[0];
    const float* h_llm   = (const float*)d_in[1];
    const float* Wq = (const float*)d_in[2];
    const float* bq = (const float*)d_in[3];
    const float* Wk = (const float*)d_in[4];
    const float* bk = (const float*)d_in[5];
    const float* Wv = (const float*)d_in[6];
    const float* bv = (const float*)d_in[7];
    const float* Wg = (const float*)d_in[8];
    const float* bg = (const float*)d_in[9];
    const float* Wb = (const float*)d_in[10];
    const float* bb = (const float*)d_in[11];
    const float* We = (const float*)d_in[12];
    float* out = (float*)d_out;

    (void)in_sizes; (void)n_in; (void)out_size;

    size_t sm1 = K1_SMEM_F * sizeof(float);
    size_t sm2 = K2_SMEM_F * sizeof(float);
    cudaFuncSetAttribute(kv_partial_kernel,
                         cudaFuncAttributeMaxDynamicSharedMemorySize, (int)sm1);
    cudaFuncSetAttribute(fused_kernel,
                         cudaFuncAttributeMaxDynamicSharedMemorySize, (int)sm2);

    kv_partial_kernel<<<dim3(16, BB), 512, sm1>>>(h_llm, Wk, Wv);
    kv_reduce_kernel<<<(BB * SS * BL) / 256, 256>>>(bk, bv);
    fused_kernel<<<dim3(TT / TOK, NE, BB), 512, sm2>>>(
        h_prime, Wq, bq, Wg, bg, Wb, bb, We, out);
}

// round 6
// speedup vs baseline: 1.8267x; 1.2507x over previous
#include <cuda_runtime.h>
#include <math.h>
#include <cstdint>

// ---------------- problem constants ----------------
#define BB     8      // batch
#define NE     4      // n_equi
#define TT     1024   // T
#define DD     1024   // D_eq
#define GG     8      // N_GROUP
#define BL     128    // BLOCKS
#define SS     64     // T_text
#define DL     2048   // d_llm
#define SCALE  0.08838834764831843f   // 128^-0.5

#define TOK    16     // tokens per block in fused kernel

// ---------------- scratch (device globals; no allocs allowed) ----------------
__device__ float g_kp[16 * BB * SS * BL];
__device__ float g_vp[16 * BB * SS * BL];
__device__ float g_k [BB * SS * BL];
__device__ float g_v [BB * SS * BL];

__device__ __forceinline__ uint32_t f2tf32(float x) {
    uint32_t r; asm("cvt.rna.tf32.f32 %0, %1;" : "=r"(r) : "f"(x)); return r;
}

// ================= kernel 1: k/v projection (known-good) =================
#define K1_SMEM_F (8192 + 2 * 128 * 129)
__global__ __launch_bounds__(512, 1)
void kv_partial_kernel(const float* __restrict__ h_llm,
                       const float* __restrict__ Wk,
                       const float* __restrict__ Wv) {
    extern __shared__ float sm[];
    float* hs  = sm;               // [s][d]  64*128
    float* wkT = sm + 8192;        // [d][o]  stride 129
    float* wvT = wkT + 128 * 129;

    const int dc  = blockIdx.x;
    const int b   = blockIdx.y;
    const int tid = threadIdx.x;

    for (int e = tid; e < SS * 32; e += 512) {
        int s = e >> 5, d4 = e & 31;
        *reinterpret_cast<float4*>(&hs[s * 128 + d4 * 4]) =
            *reinterpret_cast<const float4*>(&h_llm[(b * SS + s) * DL + dc * 128 + d4 * 4]);
    }
    for (int e = tid; e < BL * 32; e += 512) {
        int d4 = e & 31, o = e >> 5;
        float4 wk = *reinterpret_cast<const float4*>(&Wk[o * DL + dc * 128 + d4 * 4]);
        float4 wv = *reinterpret_cast<const float4*>(&Wv[o * DL + dc * 128 + d4 * 4]);
        int d0 = d4 * 4;
        wkT[(d0 + 0) * 129 + o] = wk.x; wkT[(d0 + 1) * 129 + o] = wk.y;
        wkT[(d0 + 2) * 129 + o] = wk.z; wkT[(d0 + 3) * 129 + o] = wk.w;
        wvT[(d0 + 0) * 129 + o] = wv.x; wvT[(d0 + 1) * 129 + o] = wv.y;
        wvT[(d0 + 2) * 129 + o] = wv.z; wvT[(d0 + 3) * 129 + o] = wv.w;
    }
    __syncthreads();

    const int o = tid & 127, qi = tid >> 7;
    for (int st = 0; st < 4; st++) {
        int s0 = qi * 16 + st * 4;
        float ak[4] = {0.f, 0.f, 0.f, 0.f};
        float av[4] = {0.f, 0.f, 0.f, 0.f};
#pragma unroll 4
        for (int d = 0; d < 128; d++) {
            float wk = wkT[d * 129 + o];
            float wv = wvT[d * 129 + o];
#pragma unroll
            for (int j = 0; j < 4; j++) {
                float h = hs[(s0 + j) * 128 + d];
                ak[j] = fmaf(h, wk, ak[j]);
                av[j] = fmaf(h, wv, av[j]);
            }
        }
#pragma unroll
        for (int j = 0; j < 4; j++) {
            int oidx = ((dc * BB + b) * SS + s0 + j) * BL + o;
            g_kp[oidx] = ak[j];
            g_vp[oidx] = av[j];
        }
    }
}

// ================= kernel 1b: reduce partials + bias =================
__global__ void kv_reduce_kernel(const float* __restrict__ bk,
                                 const float* __restrict__ bv) {
    int idx = blockIdx.x * 256 + threadIdx.x;
    int o = idx & 127;
    float sk = bk[o], sv = bv[o];
#pragma unroll
    for (int dc = 0; dc < 16; dc++) {
        sk += g_kp[dc * (BB * SS * BL) + idx];
        sv += g_vp[dc * (BB * SS * BL) + idx];
    }
    g_k[idx] = sk;
    g_v[idx] = sv;
}

// ================= kernel 2: fused per-token-tile kernel =================
// grid (T/16, n_equi, B), 512 threads, 1 CTA/SM.
#define OF_HT  0                          // hT[i][r] stride 132 : 16896
#define OF_WT  16896                      // WT[i][o] stride 132 : 16896
#define OF_K   (OF_WT + 16896)            // k[s][d] : 8192
#define OF_V   (OF_K + 8192)              // v[s][d] : 8192
#define OF_AT  (OF_V + 8192)              // AT[i][m] stride 16 : 2048
#define OF_Q   (OF_AT + 2048)             // Q[m][o] stride 132 : 2112
#define OF_U   (OF_Q + 2112)              // U[m][*] stride 132 : 2112
#define K2_SMEM_F (OF_U + 2112)           // 56448 floats = 225792 bytes

__device__ __forceinline__ void stage_weight_T(const float* __restrict__ Wsrc,
                                               float* __restrict__ WT, int tid) {
#pragma unroll
    for (int k = 0; k < 8; k++) {
        int e = tid + k * 512;
        int olow = e & 7, i4l = (e >> 3) & 3, ohi = (e >> 5) & 15, i4h = e >> 9;
        int o  = ohi * 8 + olow;
        int i0 = (i4h * 4 + i4l) * 4;
        float4 w = *reinterpret_cast<const float4*>(&Wsrc[o * 128 + i0]);
        WT[(i0 + 0) * 132 + o] = w.x;
        WT[(i0 + 1) * 132 + o] = w.y;
        WT[(i0 + 2) * 132 + o] = w.z;
        WT[(i0 + 3) * 132 + o] = w.w;
    }
}

// same, but store tf32-rounded bit patterns (for the mma B operand)
__device__ __forceinline__ void stage_weight_T_tf32(const float* __restrict__ Wsrc,
                                                    float* __restrict__ WT, int tid) {
#pragma unroll
    for (int k = 0; k < 8; k++) {
        int e = tid + k * 512;
        int olow = e & 7, i4l = (e >> 3) & 3, ohi = (e >> 5) & 15, i4h = e >> 9;
        int o  = ohi * 8 + olow;
        int i0 = (i4h * 4 + i4l) * 4;
        float4 w = *reinterpret_cast<const float4*>(&Wsrc[o * 128 + i0]);
        WT[(i0 + 0) * 132 + o] = __uint_as_float(f2tf32(w.x));
        WT[(i0 + 1) * 132 + o] = __uint_as_float(f2tf32(w.y));
        WT[(i0 + 2) * 132 + o] = __uint_as_float(f2tf32(w.z));
        WT[(i0 + 3) * 132 + o] = __uint_as_float(f2tf32(w.w));
    }
}

__device__ __forceinline__ void mma_tf32(float d[4], const uint32_t a[4],
                                         const uint32_t b[2]) {
    asm volatile(
        "mma.sync.aligned.m16n8k8.row.col.f32.tf32.tf32.f32 "
        "{%0,%1,%2,%3}, {%4,%5,%6,%7}, {%8,%9}, {%0,%1,%2,%3};"
        : "+f"(d[0]), "+f"(d[1]), "+f"(d[2]), "+f"(d[3])
        : "r"(a[0]), "r"(a[1]), "r"(a[2]), "r"(a[3]),
          "r"(b[0]), "r"(b[1]));
}

__global__ __launch_bounds__(512, 1)
void fused_kernel(const float* __restrict__ h_prime,
                  const float* __restrict__ Wq, const float* __restrict__ bq,
                  const float* __restrict__ Wg, const float* __restrict__ bg,
                  const float* __restrict__ Wb, const float* __restrict__ bb,
                  const float* __restrict__ We,
                  float* __restrict__ out) {
    extern __shared__ float sm[];
    float* hT  = sm + OF_HT;   // [i*132 + g*16+m]
    float* WT  = sm + OF_WT;   // [i*132 + o]
    float* ksm = sm + OF_K;    // [s*128 + d]
    float* vsm = sm + OF_V;    // [s*128 + d]
    float* AT  = sm + OF_AT;   // [k*16 + m]
    float* Q   = sm + OF_Q;    // [m*132 + o]
    float* U   = sm + OF_U;    // [m*132 + *]

    const int tid = threadIdx.x;
    const int wid = tid >> 5;
    const int t0  = blockIdx.x * TOK;
    const int n   = blockIdx.y;
    const int b   = blockIdx.z;
    const long long base = ((long long)(b * NE + n) * TT + t0) * DD;

    // ---- phase A: loads ----
#pragma unroll
    for (int k = 0; k < 8; k++) {
        int e = tid + k * 512;                 // 4096 float4
        int m = e & 15, d4 = e >> 4;
        int d = d4 * 4, g = d >> 7, i0 = d & 127;
        float4 hv = *reinterpret_cast<const float4*>(&h_prime[base + m * DD + d]);
        int r = g * 16 + m;
        hT[(i0 + 0) * 132 + r] = hv.x;
        hT[(i0 + 1) * 132 + r] = hv.y;
        hT[(i0 + 2) * 132 + r] = hv.z;
        hT[(i0 + 3) * 132 + r] = hv.w;
    }
#pragma unroll
    for (int k = 0; k < 4; k++) {
        int e = tid + k * 512;                 // 2048 float4
        int s = e >> 5, d4 = e & 31;
        *reinterpret_cast<float4*>(&ksm[s * 128 + d4 * 4]) =
            *reinterpret_cast<const float4*>(&g_k[(b * SS + s) * BL + d4 * 4]);
        *reinterpret_cast<float4*>(&vsm[s * 128 + d4 * 4]) =
            *reinterpret_cast<const float4*>(&g_v[(b * SS + s) * BL + d4 * 4]);
    }
    stage_weight_T(Wq, WT, tid);
    __syncthreads();

    // ---- phase B: group max -> AT[i][m] ----
#pragma unroll
    for (int k = 0; k < 4; k++) {
        int idx = tid + k * 512;               // 2048
        int i = idx >> 4, m = idx & 15;
        const float* row = &hT[i * 132 + m];
        float mx = row[0];
#pragma unroll
        for (int g = 1; g < GG; g++) mx = fmaxf(mx, row[g * 16]);
        AT[i * 16 + m] = mx;
    }
    __syncthreads();

    // ---- phase C: q = inv @ WqT + bq -> Q[m][o] ----
    {
        const int o = tid & 127, mq = tid >> 7;
        float bias = bq[o];
        float acc[4] = {bias, bias, bias, bias};
#pragma unroll 8
        for (int i = 0; i < 128; i++) {
            float w = WT[i * 132 + o];
            float4 a4 = *reinterpret_cast<const float4*>(&AT[i * 16 + mq * 4]);
            acc[0] = fmaf(w, a4.x, acc[0]);
            acc[1] = fmaf(w, a4.y, acc[1]);
            acc[2] = fmaf(w, a4.z, acc[2]);
            acc[3] = fmaf(w, a4.w, acc[3]);
        }
#pragma unroll
        for (int j = 0; j < 4; j++) Q[(mq * 4 + j) * 132 + o] = acc[j];
    }
    __syncthreads();

    // ---- phase D: scores -> U[m][s] ; stage Wg ----
    stage_weight_T(Wg, WT, tid);
    {
        const int m = tid & 15, sh = tid >> 4;
        float a0 = 0.f, a1 = 0.f;
#pragma unroll 8
        for (int d4 = 0; d4 < 32; d4++) {
            float4 q4 = *reinterpret_cast<const float4*>(&Q[m * 132 + d4 * 4]);
            float4 ka = *reinterpret_cast<const float4*>(&ksm[sh * 128 + d4 * 4]);
            float4 kb = *reinterpret_cast<const float4*>(&ksm[(sh + 32) * 128 + d4 * 4]);
            a0 = fmaf(q4.x, ka.x, a0); a0 = fmaf(q4.y, ka.y, a0);
            a0 = fmaf(q4.z, ka.z, a0); a0 = fmaf(q4.w, ka.w, a0);
            a1 = fmaf(q4.x, kb.x, a1); a1 = fmaf(q4.y, kb.y, a1);
            a1 = fmaf(q4.z, kb.z, a1); a1 = fmaf(q4.w, kb.w, a1);
        }
        U[m * 132 + sh]      = a0 * SCALE;
        U[m * 132 + sh + 32] = a1 * SCALE;
    }
    __syncthreads();

    // ---- phase E: softmax, one warp per row ----
    {
        const int w = wid, l = tid & 31;
        float x0 = U[w * 132 + l];
        float x1 = U[w * 132 + l + 32];
        float mx = fmaxf(x0, x1);
#pragma unroll
        for (int off = 16; off > 0; off >>= 1)
            mx = fmaxf(mx, __shfl_xor_sync(0xffffffffu, mx, off));
        float e0 = __expf(x0 - mx), e1 = __expf(x1 - mx);
        float s = e0 + e1;
#pragma unroll
        for (int off = 16; off > 0; off >>= 1)
            s += __shfl_xor_sync(0xffffffffu, s, off);
        float inv = 1.f / s;
        U[w * 132 + l]      = e0 * inv;
        U[w * 132 + l + 32] = e1 * inv;
    }
    __syncthreads();

    // ---- phase F: ctx = attn @ v -> AT[d][m] ----
    {
        const int m = tid & 15, dh = tid >> 4;
        const int d0 = dh * 4;
        float acc[4] = {0.f, 0.f, 0.f, 0.f};
#pragma unroll 8
        for (int s = 0; s < SS; s++) {
            float u = U[m * 132 + s];
            float4 v4 = *reinterpret_cast<const float4*>(&vsm[s * 128 + d0]);
            acc[0] = fmaf(u, v4.x, acc[0]);
            acc[1] = fmaf(u, v4.y, acc[1]);
            acc[2] = fmaf(u, v4.z, acc[2]);
            acc[3] = fmaf(u, v4.w, acc[3]);
        }
#pragma unroll
        for (int j = 0; j < 4; j++) AT[(d0 + j) * 16 + m] = acc[j];
    }
    __syncthreads();

    // ---- phase G: gamma = ctx @ WgT + bg -> Q ----
    {
        const int o = tid & 127, mq = tid >> 7;
        float bias = bg[o];
        float acc[4] = {bias, bias, bias, bias};
#pragma unroll 8
        for (int i = 0; i < 128; i++) {
            float w = WT[i * 132 + o];
            float4 a4 = *reinterpret_cast<const float4*>(&AT[i * 16 + mq * 4]);
            acc[0] = fmaf(w, a4.x, acc[0]);
            acc[1] = fmaf(w, a4.y, acc[1]);
            acc[2] = fmaf(w, a4.z, acc[2]);
            acc[3] = fmaf(w, a4.w, acc[3]);
        }
#pragma unroll
        for (int j = 0; j < 4; j++) Q[(mq * 4 + j) * 132 + o] = acc[j];
    }
    __syncthreads();

    stage_weight_T(Wb, WT, tid);
    __syncthreads();

    // ---- phase H: beta = ctx @ WbT + bb -> U ----
    {
        const int o = tid & 127, mq = tid >> 7;
        float bias = bb[o];
        float acc[4] = {bias, bias, bias, bias};
#pragma unroll 8
        for (int i = 0; i < 128; i++) {
            float w = WT[i * 132 + o];
            float4 a4 = *reinterpret_cast<const float4*>(&AT[i * 16 + mq * 4]);
            acc[0] = fmaf(w, a4.x, acc[0]);
            acc[1] = fmaf(w, a4.y, acc[1]);
            acc[2] = fmaf(w, a4.z, acc[2]);
            acc[3] = fmaf(w, a4.w, acc[3]);
        }
#pragma unroll
        for (int j = 0; j < 4; j++) U[(mq * 4 + j) * 132 + o] = acc[j];
    }
    __syncthreads();

    stage_weight_T_tf32(We, WT, tid);
    __syncthreads();

    // ---- phase J: equi GEMM via mma.sync tf32 + epilogue ----
    {
        const int l  = tid & 31;
        const int r0 = (wid >> 2) * 32;      // 32-row warp tile
        const int o0 = (wid & 3) * 32;       // 32-col warp tile
        const int lr = l >> 2, lc = l & 3;

        float d[2][4][4];
#pragma unroll
        for (int mt = 0; mt < 2; mt++)
#pragma unroll
            for (int nt = 0; nt < 4; nt++)
#pragma unroll
                for (int j = 0; j < 4; j++) d[mt][nt][j] = 0.f;

#pragma unroll 2
        for (int k = 0; k < 16; k++) {
            const int i0 = k * 8;
            uint32_t a[2][4], bfr[4][2];
#pragma unroll
            for (int mt = 0; mt < 2; mt++) {
                const int rb = r0 + mt * 16 + lr;
                a[mt][0] = f2tf32(hT[(i0 + lc) * 132 + rb]);
                a[mt][1] = f2tf32(hT[(i0 + lc) * 132 + rb + 8]);
                a[mt][2] = f2tf32(hT[(i0 + lc + 4) * 132 + rb]);
                a[mt][3] = f2tf32(hT[(i0 + lc + 4) * 132 + rb + 8]);
            }
#pragma unroll
            for (int nt = 0; nt < 4; nt++) {
                const int ob = o0 + nt * 8 + lr;   // col = lane>>2 (0..7)
                bfr[nt][0] = __float_as_uint(WT[(i0 + lc) * 132 + ob]);
                bfr[nt][1] = __float_as_uint(WT[(i0 + lc + 4) * 132 + ob]);
            }
#pragma unroll
            for (int mt = 0; mt < 2; mt++)
#pragma unroll
                for (int nt = 0; nt < 4; nt++)
                    mma_tf32(d[mt][nt], a[mt], bfr[nt]);
        }

        // epilogue from C fragments
#pragma unroll
        for (int mt = 0; mt < 2; mt++) {
#pragma unroll
            for (int rh = 0; rh < 2; rh++) {
                const int r = r0 + mt * 16 + lr + rh * 8;
                const int m = r & 15, g = r >> 4;
                float* orow = out + base + m * DD + g * 128;
#pragma unroll
                for (int nt = 0; nt < 4; nt++) {
                    const int o = o0 + nt * 8 + lc * 2;
                    float e0 = d[mt][nt][rh * 2 + 0];
                    float e1 = d[mt][nt][rh * 2 + 1];
                    float2 gam = *reinterpret_cast<const float2*>(&Q[m * 132 + o]);
                    float2 bet = *reinterpret_cast<const float2*>(&U[m * 132 + o]);
                    float c0 = AT[(o + 0) * 16 + m];
                    float c1 = AT[(o + 1) * 16 + m];
                    float res0 = hT[(o + 0) * 132 + r];
                    float res1 = hT[(o + 1) * 132 + r];
                    float g0 = 1.f / (1.f + __expf(-c0));
                    float g1 = 1.f / (1.f + __expf(-c1));
                    float2 ov;
                    ov.x = res0 + g0 * (gam.x * e0 + bet.x);
                    ov.y = res1 + g1 * (gam.y * e1 + bet.y);
                    *reinterpret_cast<float2*>(&orow[o]) = ov;
                }
            }
        }
    }
}

// ================= launcher =================
extern "C" void kernel_launch(void* const* d_in, const int* in_sizes, int n_in,
                              void* d_out, int out_size) {
    const float* h_prime = (const float*)d_in[0];
    const float* h_llm   = (const float*)d_in[1];
    const float* Wq = (const float*)d_in[2];
    const float* bq = (const float*)d_in[3];
    const float* Wk = (const float*)d_in[4];
    const float* bk = (const float*)d_in[5];
    const float* Wv = (const float*)d_in[6];
    const float* bv = (const float*)d_in[7];
    const float* Wg = (const float*)d_in[8];
    const float* bg = (const float*)d_in[9];
    const float* Wb = (const float*)d_in[10];
    const float* bb = (const float*)d_in[11];
    const float* We = (const float*)d_in[12];
    float* out = (float*)d_out;

    (void)in_sizes; (void)n_in; (void)out_size;

    size_t sm1 = K1_SMEM_F * sizeof(float);
    size_t sm2 = K2_SMEM_F * sizeof(float);
    cudaFuncSetAttribute(kv_partial_kernel,
                         cudaFuncAttributeMaxDynamicSharedMemorySize, (int)sm1);
    cudaFuncSetAttribute(fused_kernel,
                         cudaFuncAttributeMaxDynamicSharedMemorySize, (int)sm2);

    kv_partial_kernel<<<dim3(16, BB), 512, sm1>>>(h_llm, Wk, Wv);
    kv_reduce_kernel<<<(BB * SS * BL) / 256, 256>>>(bk, bv);
    fused_kernel<<<dim3(TT / TOK, NE, BB), 512, sm2>>>(
        h_prime, Wq, bq, Wg, bg, Wb, bb, We, out);
}

// round 7
// speedup vs baseline: 2.2758x; 1.2459x over previous
#include <cuda_runtime.h>
#include <math.h>
#include <cstdint>

// ---------------- problem constants ----------------
#define BB     8      // batch
#define NE     4      // n_equi
#define TT     1024   // T
#define DD     1024   // D_eq
#define GG     8      // N_GROUP
#define BL     128    // BLOCKS
#define SS     64     // T_text
#define DL     2048   // d_llm
#define SCALE  0.08838834764831843f   // 128^-0.5

#define TOK    16     // tokens per block in fused kernel

// ---------------- scratch (device globals; no allocs allowed) ----------------
__device__ float g_kp[16 * BB * SS * BL];
__device__ float g_vp[16 * BB * SS * BL];
__device__ float g_k [BB * SS * BL];
__device__ float g_v [BB * SS * BL];

__device__ __forceinline__ uint32_t f2tf32(float x) {
    uint32_t r; asm("cvt.rna.tf32.f32 %0, %1;" : "=r"(r) : "f"(x)); return r;
}

__device__ __forceinline__ void mma_tf32(float d[4], const uint32_t a[4],
                                         const uint32_t b[2]) {
    asm volatile(
        "mma.sync.aligned.m16n8k8.row.col.f32.tf32.tf32.f32 "
        "{%0,%1,%2,%3}, {%4,%5,%6,%7}, {%8,%9}, {%0,%1,%2,%3};"
        : "+f"(d[0]), "+f"(d[1]), "+f"(d[2]), "+f"(d[3])
        : "r"(a[0]), "r"(a[1]), "r"(a[2]), "r"(a[3]),
          "r"(b[0]), "r"(b[1]));
}

// ================= kernel 1: k/v projection (known-good, fp32) =================
#define K1_SMEM_F (8192 + 2 * 128 * 129)
__global__ __launch_bounds__(512, 1)
void kv_partial_kernel(const float* __restrict__ h_llm,
                       const float* __restrict__ Wk,
                       const float* __restrict__ Wv) {
    extern __shared__ float sm[];
    float* hs  = sm;               // [s][d]  64*128
    float* wkT = sm + 8192;        // [d][o]  stride 129
    float* wvT = wkT + 128 * 129;

    const int dc  = blockIdx.x;
    const int b   = blockIdx.y;
    const int tid = threadIdx.x;

    for (int e = tid; e < SS * 32; e += 512) {
        int s = e >> 5, d4 = e & 31;
        *reinterpret_cast<float4*>(&hs[s * 128 + d4 * 4]) =
            *reinterpret_cast<const float4*>(&h_llm[(b * SS + s) * DL + dc * 128 + d4 * 4]);
    }
    for (int e = tid; e < BL * 32; e += 512) {
        int d4 = e & 31, o = e >> 5;
        float4 wk = *reinterpret_cast<const float4*>(&Wk[o * DL + dc * 128 + d4 * 4]);
        float4 wv = *reinterpret_cast<const float4*>(&Wv[o * DL + dc * 128 + d4 * 4]);
        int d0 = d4 * 4;
        wkT[(d0 + 0) * 129 + o] = wk.x; wkT[(d0 + 1) * 129 + o] = wk.y;
        wkT[(d0 + 2) * 129 + o] = wk.z; wkT[(d0 + 3) * 129 + o] = wk.w;
        wvT[(d0 + 0) * 129 + o] = wv.x; wvT[(d0 + 1) * 129 + o] = wv.y;
        wvT[(d0 + 2) * 129 + o] = wv.z; wvT[(d0 + 3) * 129 + o] = wv.w;
    }
    __syncthreads();

    const int o = tid & 127, qi = tid >> 7;
    for (int st = 0; st < 4; st++) {
        int s0 = qi * 16 + st * 4;
        float ak[4] = {0.f, 0.f, 0.f, 0.f};
        float av[4] = {0.f, 0.f, 0.f, 0.f};
#pragma unroll 4
        for (int d = 0; d < 128; d++) {
            float wk = wkT[d * 129 + o];
            float wv = wvT[d * 129 + o];
#pragma unroll
            for (int j = 0; j < 4; j++) {
                float h = hs[(s0 + j) * 128 + d];
                ak[j] = fmaf(h, wk, ak[j]);
                av[j] = fmaf(h, wv, av[j]);
            }
        }
#pragma unroll
        for (int j = 0; j < 4; j++) {
            int oidx = ((dc * BB + b) * SS + s0 + j) * BL + o;
            g_kp[oidx] = ak[j];
            g_vp[oidx] = av[j];
        }
    }
}

// ================= kernel 1b: reduce partials + bias =================
__global__ void kv_reduce_kernel(const float* __restrict__ bk,
                                 const float* __restrict__ bv) {
    int idx = blockIdx.x * 256 + threadIdx.x;
    int o = idx & 127;
    float sk = bk[o], sv = bv[o];
#pragma unroll
    for (int dc = 0; dc < 16; dc++) {
        sk += g_kp[dc * (BB * SS * BL) + idx];
        sv += g_vp[dc * (BB * SS * BL) + idx];
    }
    g_k[idx] = sk;
    g_v[idx] = sv;
}

// ================= kernel 2: fused, all-mma =================
// grid (T/16, n_equi, B), 512 threads, 1 CTA/SM.
#define OF_HT  0                          // hT[i][r] stride 132 : 16896
#define OF_K   16896                      // k[s][d] stride 132 : 8448
#define OF_V   (OF_K + 8448)              // v[s][d] stride 136 : 8704
#define OF_AT  (OF_V + 8704)              // AT[i][m] stride 24 : 3072
#define OF_Q   (OF_AT + 3072)             // Q[m][o] stride 132 : 2112
#define OF_U   (OF_Q + 2112)              // U[m][*] stride 132 : 2112
#define K2_SMEM_F (OF_U + 2112)           // 41344 floats = 165376 bytes

__global__ __launch_bounds__(512, 1)
void fused_kernel(const float* __restrict__ h_prime,
                  const float* __restrict__ Wq, const float* __restrict__ bq,
                  const float* __restrict__ Wg, const float* __restrict__ bg,
                  const float* __restrict__ Wb, const float* __restrict__ bb,
                  const float* __restrict__ We,
                  float* __restrict__ out) {
    extern __shared__ float sm[];
    float* hT  = sm + OF_HT;   // [i*132 + g*16+m]
    float* ksm = sm + OF_K;    // [s*132 + d]
    float* vsm = sm + OF_V;    // [s*136 + d]
    float* AT  = sm + OF_AT;   // [k*24 + m]  (inv feat -> ctx)
    float* Q   = sm + OF_Q;    // [m*132 + o] (q -> gamma)
    float* U   = sm + OF_U;    // [m*132 + *] (scores -> beta)

    const int tid = threadIdx.x;
    const int wid = tid >> 5;
    const int l   = tid & 31;
    const int lr  = l >> 2;     // 0..7
    const int lc  = l & 3;      // 0..3
    const int t0  = blockIdx.x * TOK;
    const int n   = blockIdx.y;
    const int b   = blockIdx.z;
    const long long base = ((long long)(b * NE + n) * TT + t0) * DD;

    // ---- phase A: loads ----
#pragma unroll
    for (int k = 0; k < 8; k++) {
        int e = tid + k * 512;                 // 4096 float4
        int m = e & 15, d4 = e >> 4;
        int d = d4 * 4, g = d >> 7, i0 = d & 127;
        float4 hv = *reinterpret_cast<const float4*>(&h_prime[base + m * DD + d]);
        int r = g * 16 + m;
        hT[(i0 + 0) * 132 + r] = hv.x;
        hT[(i0 + 1) * 132 + r] = hv.y;
        hT[(i0 + 2) * 132 + r] = hv.z;
        hT[(i0 + 3) * 132 + r] = hv.w;
    }
#pragma unroll
    for (int k = 0; k < 4; k++) {
        int e = tid + k * 512;                 // 2048 float4
        int s = e >> 5, d4 = e & 31;
        *reinterpret_cast<float4*>(&ksm[s * 132 + d4 * 4]) =
            *reinterpret_cast<const float4*>(&g_k[(b * SS + s) * BL + d4 * 4]);
        *reinterpret_cast<float4*>(&vsm[s * 136 + d4 * 4]) =
            *reinterpret_cast<const float4*>(&g_v[(b * SS + s) * BL + d4 * 4]);
    }
    __syncthreads();

    // ---- phase B: group max -> AT[i][m] (stride 24) ----
#pragma unroll
    for (int k = 0; k < 4; k++) {
        int idx = tid + k * 512;               // 2048
        int i = idx >> 4, m = idx & 15;
        const float* row = &hT[i * 132 + m];
        float mx = row[0];
#pragma unroll
        for (int g = 1; g < GG; g++) mx = fmaxf(mx, row[g * 16]);
        AT[i * 24 + m] = mx;
    }
    __syncthreads();

    // ---- phase C: q = inv @ WqT + bq (mma) -> Q[m][o] ----
    {
        const int o8 = wid * 8;                // this warp's 8 output cols
        float d[4] = {0.f, 0.f, 0.f, 0.f};
#pragma unroll 4
        for (int kk = 0; kk < 16; kk++) {
            const int i0 = kk * 8;
            uint32_t a[4], bf[2];
            a[0] = f2tf32(AT[(i0 + lc) * 24 + lr]);
            a[1] = f2tf32(AT[(i0 + lc) * 24 + lr + 8]);
            a[2] = f2tf32(AT[(i0 + lc + 4) * 24 + lr]);
            a[3] = f2tf32(AT[(i0 + lc + 4) * 24 + lr + 8]);
            bf[0] = f2tf32(Wq[(o8 + lr) * 128 + i0 + lc]);
            bf[1] = f2tf32(Wq[(o8 + lr) * 128 + i0 + lc + 4]);
            mma_tf32(d, a, bf);
        }
        float2 bv2 = *reinterpret_cast<const float2*>(&bq[o8 + lc * 2]);
        Q[lr * 132 + o8 + lc * 2]           = d[0] + bv2.x;
        Q[lr * 132 + o8 + lc * 2 + 1]       = d[1] + bv2.y;
        Q[(lr + 8) * 132 + o8 + lc * 2]     = d[2] + bv2.x;
        Q[(lr + 8) * 132 + o8 + lc * 2 + 1] = d[3] + bv2.y;
    }
    __syncthreads();

    // ---- phase D: scores = q.k * SCALE (mma, 8 warps) -> U[m][s] ----
    if (wid < 8) {
        const int s8 = wid * 8;
        float d[4] = {0.f, 0.f, 0.f, 0.f};
#pragma unroll 4
        for (int kk = 0; kk < 16; kk++) {
            const int i0 = kk * 8;
            uint32_t a[4], bf[2];
            a[0] = f2tf32(Q[lr * 132 + i0 + lc]);
            a[1] = f2tf32(Q[(lr + 8) * 132 + i0 + lc]);
            a[2] = f2tf32(Q[lr * 132 + i0 + lc + 4]);
            a[3] = f2tf32(Q[(lr + 8) * 132 + i0 + lc + 4]);
            bf[0] = f2tf32(ksm[(s8 + lr) * 132 + i0 + lc]);
            bf[1] = f2tf32(ksm[(s8 + lr) * 132 + i0 + lc + 4]);
            mma_tf32(d, a, bf);
        }
        U[lr * 132 + s8 + lc * 2]           = d[0] * SCALE;
        U[lr * 132 + s8 + lc * 2 + 1]       = d[1] * SCALE;
        U[(lr + 8) * 132 + s8 + lc * 2]     = d[2] * SCALE;
        U[(lr + 8) * 132 + s8 + lc * 2 + 1] = d[3] * SCALE;
    }
    __syncthreads();

    // ---- phase E: softmax, one warp per row ----
    {
        float x0 = U[wid * 132 + l];
        float x1 = U[wid * 132 + l + 32];
        float mx = fmaxf(x0, x1);
#pragma unroll
        for (int off = 16; off > 0; off >>= 1)
            mx = fmaxf(mx, __shfl_xor_sync(0xffffffffu, mx, off));
        float e0 = __expf(x0 - mx), e1 = __expf(x1 - mx);
        float s = e0 + e1;
#pragma unroll
        for (int off = 16; off > 0; off >>= 1)
            s += __shfl_xor_sync(0xffffffffu, s, off);
        float inv = 1.f / s;
        U[wid * 132 + l]      = e0 * inv;
        U[wid * 132 + l + 32] = e1 * inv;
    }
    __syncthreads();

    // ---- phase F: ctx = attn @ v (mma) -> AT[d][m] (stride 24) ----
    {
        const int o8 = wid * 8;                // 8 d-cols per warp
        float d[4] = {0.f, 0.f, 0.f, 0.f};
#pragma unroll 4
        for (int kk = 0; kk < 8; kk++) {
            const int i0 = kk * 8;
            uint32_t a[4], bf[2];
            a[0] = f2tf32(U[lr * 132 + i0 + lc]);
            a[1] = f2tf32(U[(lr + 8) * 132 + i0 + lc]);
            a[2] = f2tf32(U[lr * 132 + i0 + lc + 4]);
            a[3] = f2tf32(U[(lr + 8) * 132 + i0 + lc + 4]);
            bf[0] = f2tf32(vsm[(i0 + lc) * 136 + o8 + lr]);
            bf[1] = f2tf32(vsm[(i0 + lc + 4) * 136 + o8 + lr]);
            mma_tf32(d, a, bf);
        }
        AT[(o8 + lc * 2) * 24 + lr]         = d[0];
        AT[(o8 + lc * 2 + 1) * 24 + lr]     = d[1];
        AT[(o8 + lc * 2) * 24 + lr + 8]     = d[2];
        AT[(o8 + lc * 2 + 1) * 24 + lr + 8] = d[3];
    }
    __syncthreads();

    // ---- phase G: gamma & beta (merged mma) -> Q (gamma), U (beta) ----
    {
        const int o8 = wid * 8;
        float dg[4] = {0.f, 0.f, 0.f, 0.f};
        float db[4] = {0.f, 0.f, 0.f, 0.f};
#pragma unroll 4
        for (int kk = 0; kk < 16; kk++) {
            const int i0 = kk * 8;
            uint32_t a[4], bG[2], bB[2];
            a[0] = f2tf32(AT[(i0 + lc) * 24 + lr]);
            a[1] = f2tf32(AT[(i0 + lc) * 24 + lr + 8]);
            a[2] = f2tf32(AT[(i0 + lc + 4) * 24 + lr]);
            a[3] = f2tf32(AT[(i0 + lc + 4) * 24 + lr + 8]);
            bG[0] = f2tf32(Wg[(o8 + lr) * 128 + i0 + lc]);
            bG[1] = f2tf32(Wg[(o8 + lr) * 128 + i0 + lc + 4]);
            bB[0] = f2tf32(Wb[(o8 + lr) * 128 + i0 + lc]);
            bB[1] = f2tf32(Wb[(o8 + lr) * 128 + i0 + lc + 4]);
            mma_tf32(dg, a, bG);
            mma_tf32(db, a, bB);
        }
        float2 bgv = *reinterpret_cast<const float2*>(&bg[o8 + lc * 2]);
        float2 bbv = *reinterpret_cast<const float2*>(&bb[o8 + lc * 2]);
        Q[lr * 132 + o8 + lc * 2]           = dg[0] + bgv.x;
        Q[lr * 132 + o8 + lc * 2 + 1]       = dg[1] + bgv.y;
        Q[(lr + 8) * 132 + o8 + lc * 2]     = dg[2] + bgv.x;
        Q[(lr + 8) * 132 + o8 + lc * 2 + 1] = dg[3] + bgv.y;
        U[lr * 132 + o8 + lc * 2]           = db[0] + bbv.x;
        U[lr * 132 + o8 + lc * 2 + 1]       = db[1] + bbv.y;
        U[(lr + 8) * 132 + o8 + lc * 2]     = db[2] + bbv.x;
        U[(lr + 8) * 132 + o8 + lc * 2 + 1] = db[3] + bbv.y;
    }
    __syncthreads();

    // ---- phase J: equi GEMM (mma, We direct from gmem) + epilogue ----
    {
        const int r0 = (wid >> 2) * 32;      // 32-row warp tile
        const int o0 = (wid & 3) * 32;       // 32-col warp tile

        float d[2][4][4];
#pragma unroll
        for (int mt = 0; mt < 2; mt++)
#pragma unroll
            for (int nt = 0; nt < 4; nt++)
#pragma unroll
                for (int j = 0; j < 4; j++) d[mt][nt][j] = 0.f;

#pragma unroll 2
        for (int k = 0; k < 16; k++) {
            const int i0 = k * 8;
            uint32_t a[2][4], bfr[4][2];
#pragma unroll
            for (int mt = 0; mt < 2; mt++) {
                const int rb = r0 + mt * 16 + lr;
                a[mt][0] = f2tf32(hT[(i0 + lc) * 132 + rb]);
                a[mt][1] = f2tf32(hT[(i0 + lc) * 132 + rb + 8]);
                a[mt][2] = f2tf32(hT[(i0 + lc + 4) * 132 + rb]);
                a[mt][3] = f2tf32(hT[(i0 + lc + 4) * 132 + rb + 8]);
            }
#pragma unroll
            for (int nt = 0; nt < 4; nt++) {
                const int ob = o0 + nt * 8 + lr;
                bfr[nt][0] = f2tf32(We[ob * 128 + i0 + lc]);
                bfr[nt][1] = f2tf32(We[ob * 128 + i0 + lc + 4]);
            }
#pragma unroll
            for (int mt = 0; mt < 2; mt++)
#pragma unroll
                for (int nt = 0; nt < 4; nt++)
                    mma_tf32(d[mt][nt], a[mt], bfr[nt]);
        }

        // epilogue from C fragments
#pragma unroll
        for (int mt = 0; mt < 2; mt++) {
#pragma unroll
            for (int rh = 0; rh < 2; rh++) {
                const int r = r0 + mt * 16 + lr + rh * 8;
                const int m = r & 15, g = r >> 4;
                float* orow = out + base + m * DD + g * 128;
#pragma unroll
                for (int nt = 0; nt < 4; nt++) {
                    const int o = o0 + nt * 8 + lc * 2;
                    float e0 = d[mt][nt][rh * 2 + 0];
                    float e1 = d[mt][nt][rh * 2 + 1];
                    float2 gam = *reinterpret_cast<const float2*>(&Q[m * 132 + o]);
                    float2 bet = *reinterpret_cast<const float2*>(&U[m * 132 + o]);
                    float c0 = AT[(o + 0) * 24 + m];
                    float c1 = AT[(o + 1) * 24 + m];
                    float res0 = hT[(o + 0) * 132 + r];
                    float res1 = hT[(o + 1) * 132 + r];
                    float g0 = 1.f / (1.f + __expf(-c0));
                    float g1 = 1.f / (1.f + __expf(-c1));
                    float2 ov;
                    ov.x = res0 + g0 * (gam.x * e0 + bet.x);
                    ov.y = res1 + g1 * (gam.y * e1 + bet.y);
                    *reinterpret_cast<float2*>(&orow[o]) = ov;
                }
            }
        }
    }
}

// ================= launcher =================
extern "C" void kernel_launch(void* const* d_in, const int* in_sizes, int n_in,
                              void* d_out, int out_size) {
    const float* h_prime = (const float*)d_in[0];
    const float* h_llm   = (const float*)d_in[1];
    const float* Wq = (const float*)d_in[2];
    const float* bq = (const float*)d_in[3];
    const float* Wk = (const float*)d_in[4];
    const float* bk = (const float*)d_in[5];
    const float* Wv = (const float*)d_in[6];
    const float* bv = (const float*)d_in[7];
    const float* Wg = (const float*)d_in[8];
    const float* bg = (const float*)d_in[9];
    const float* Wb = (const float*)d_in[10];
    const float* bb = (const float*)d_in[11];
    const float* We = (const float*)d_in[12];
    float* out = (float*)d_out;

    (void)in_sizes; (void)n_in; (void)out_size;

    size_t sm1 = K1_SMEM_F * sizeof(float);
    size_t sm2 = K2_SMEM_F * sizeof(float);
    cudaFuncSetAttribute(kv_partial_kernel,
                         cudaFuncAttributeMaxDynamicSharedMemorySize, (int)sm1);
    cudaFuncSetAttribute(fused_kernel,
                         cudaFuncAttributeMaxDynamicSharedMemorySize, (int)sm2);

    kv_partial_kernel<<<dim3(16, BB), 512, sm1>>>(h_llm, Wk, Wv);
    kv_reduce_kernel<<<(BB * SS * BL) / 256, 256>>>(bk, bv);
    fused_kernel<<<dim3(TT / TOK, NE, BB), 512, sm2>>>(
        h_prime, Wq, bq, Wg, bg, Wb, bb, We, out);
}

// round 9
// speedup vs baseline: 3.9086x; 1.7174x over previous
#include <cuda_runtime.h>
#include <math.h>
#include <cstdint>

// ---------------- problem constants ----------------
#define BB     8      // batch
#define NE     4      // n_equi
#define TT     1024   // T
#define DD     1024   // D_eq
#define GG     8      // N_GROUP
#define BL     128    // BLOCKS
#define SS     64     // T_text
#define DL     2048   // d_llm
#define SCALE  0.08838834764831843f   // 128^-0.5

#define TOK    16     // tokens per block in fused kernel

// ---------------- scratch (device globals; no allocs allowed) ----------------
__device__ float g_kp[16 * BB * SS * BL];
__device__ float g_vp[16 * BB * SS * BL];
__device__ float g_k [BB * SS * BL];
__device__ float g_v [BB * SS * BL];

// fragment-ordered weights (pre-tf32). wq/wg/wb: [wid 16][kk 16][lane 32]
// we: [oc 4][k 16][ntp 2][lane 32] (uint4 packs 2 n-tiles)
__device__ uint2 g_wqf[16 * 16 * 32];
__device__ uint2 g_wgf[16 * 16 * 32];
__device__ uint2 g_wbf[16 * 16 * 32];
__device__ uint4 g_wef[4 * 16 * 2 * 32];

__device__ __forceinline__ uint32_t f2tf32(float x) {
    uint32_t r; asm("cvt.rna.tf32.f32 %0, %1;" : "=r"(r) : "f"(x)); return r;
}

__device__ __forceinline__ void mma_tf32(float d[4], const uint32_t a[4],
                                         const uint32_t b[2]) {
    asm volatile(
        "mma.sync.aligned.m16n8k8.row.col.f32.tf32.tf32.f32 "
        "{%0,%1,%2,%3}, {%4,%5,%6,%7}, {%8,%9}, {%0,%1,%2,%3};"
        : "+f"(d[0]), "+f"(d[1]), "+f"(d[2]), "+f"(d[3])
        : "r"(a[0]), "r"(a[1]), "r"(a[2]), "r"(a[3]),
          "r"(b[0]), "r"(b[1]));
}

// ================= kernel 0: fragment prep (12288 threads) =================
__global__ void frag_prep_kernel(const float* __restrict__ Wq,
                                 const float* __restrict__ Wg,
                                 const float* __restrict__ Wb,
                                 const float* __restrict__ We) {
    int idx = blockIdx.x * 256 + threadIdx.x;
    if (idx < 8192) {
        int lane = idx & 31, kk = (idx >> 5) & 15, w = idx >> 9;
        int lr = lane >> 2, lc = lane & 3;
        int ofs = (w * 8 + lr) * 128 + kk * 8 + lc;
        g_wqf[idx] = make_uint2(f2tf32(Wq[ofs]), f2tf32(Wq[ofs + 4]));
        g_wgf[idx] = make_uint2(f2tf32(Wg[ofs]), f2tf32(Wg[ofs + 4]));
        g_wbf[idx] = make_uint2(f2tf32(Wb[ofs]), f2tf32(Wb[ofs + 4]));
    } else if (idx < 8192 + 4096) {
        int j = idx - 8192;
        int lane = j & 31, ntp = (j >> 5) & 1, k = (j >> 6) & 15, oc = j >> 10;
        int lr = lane >> 2, lc = lane & 3;
        int r0 = (oc * 32 + ntp * 16 + lr) * 128 + k * 8 + lc;
        int r1 = r0 + 8 * 128;
        g_wef[j] = make_uint4(f2tf32(We[r0]), f2tf32(We[r0 + 4]),
                              f2tf32(We[r1]), f2tf32(We[r1 + 4]));
    }
}

// ================= kernel 1: k/v projection (fp32) =================
#define K1_SMEM_F (8192 + 2 * 128 * 129)
__global__ __launch_bounds__(512, 1)
void kv_partial_kernel(const float* __restrict__ h_llm,
                       const float* __restrict__ Wk,
                       const float* __restrict__ Wv) {
    extern __shared__ float sm[];
    float* hs  = sm;               // [s][d]  64*128
    float* wkT = sm + 8192;        // [d][o]  stride 129
    float* wvT = wkT + 128 * 129;

    const int dc  = blockIdx.x;
    const int b   = blockIdx.y;
    const int tid = threadIdx.x;

    for (int e = tid; e < SS * 32; e += 512) {
        int s = e >> 5, d4 = e & 31;
        *reinterpret_cast<float4*>(&hs[s * 128 + d4 * 4]) =
            *reinterpret_cast<const float4*>(&h_llm[(b * SS + s) * DL + dc * 128 + d4 * 4]);
    }
    for (int e = tid; e < BL * 32; e += 512) {
        int d4 = e & 31, o = e >> 5;
        float4 wk = *reinterpret_cast<const float4*>(&Wk[o * DL + dc * 128 + d4 * 4]);
        float4 wv = *reinterpret_cast<const float4*>(&Wv[o * DL + dc * 128 + d4 * 4]);
        int d0 = d4 * 4;
        wkT[(d0 + 0) * 129 + o] = wk.x; wkT[(d0 + 1) * 129 + o] = wk.y;
        wkT[(d0 + 2) * 129 + o] = wk.z; wkT[(d0 + 3) * 129 + o] = wk.w;
        wvT[(d0 + 0) * 129 + o] = wv.x; wvT[(d0 + 1) * 129 + o] = wv.y;
        wvT[(d0 + 2) * 129 + o] = wv.z; wvT[(d0 + 3) * 129 + o] = wv.w;
    }
    __syncthreads();

    const int o = tid & 127, qi = tid >> 7;
    for (int st = 0; st < 4; st++) {
        int s0 = qi * 16 + st * 4;
        float ak[4] = {0.f, 0.f, 0.f, 0.f};
        float av[4] = {0.f, 0.f, 0.f, 0.f};
#pragma unroll 4
        for (int d4 = 0; d4 < 32; d4++) {
            float4 h0 = *reinterpret_cast<const float4*>(&hs[(s0 + 0) * 128 + d4 * 4]);
            float4 h1 = *reinterpret_cast<const float4*>(&hs[(s0 + 1) * 128 + d4 * 4]);
            float4 h2 = *reinterpret_cast<const float4*>(&hs[(s0 + 2) * 128 + d4 * 4]);
            float4 h3 = *reinterpret_cast<const float4*>(&hs[(s0 + 3) * 128 + d4 * 4]);
            const float hh[4][4] = {{h0.x, h0.y, h0.z, h0.w},
                                    {h1.x, h1.y, h1.z, h1.w},
                                    {h2.x, h2.y, h2.z, h2.w},
                                    {h3.x, h3.y, h3.z, h3.w}};
#pragma unroll
            for (int jd = 0; jd < 4; jd++) {
                float wk = wkT[(d4 * 4 + jd) * 129 + o];
                float wv = wvT[(d4 * 4 + jd) * 129 + o];
#pragma unroll
                for (int j = 0; j < 4; j++) {
                    ak[j] = fmaf(hh[j][jd], wk, ak[j]);
                    av[j] = fmaf(hh[j][jd], wv, av[j]);
                }
            }
        }
#pragma unroll
        for (int j = 0; j < 4; j++) {
            int oidx = ((dc * BB + b) * SS + s0 + j) * BL + o;
            g_kp[oidx] = ak[j];
            g_vp[oidx] = av[j];
        }
    }
}

// ================= kernel 1b: reduce partials + bias =================
__global__ void kv_reduce_kernel(const float* __restrict__ bk,
                                 const float* __restrict__ bv) {
    int idx = blockIdx.x * 256 + threadIdx.x;
    int o = idx & 127;
    float sk = bk[o], sv = bv[o];
#pragma unroll
    for (int dc = 0; dc < 16; dc++) {
        sk += g_kp[dc * (BB * SS * BL) + idx];
        sv += g_vp[dc * (BB * SS * BL) + idx];
    }
    g_k[idx] = sk;
    g_v[idx] = sv;
}

// ================= kernel 2: fused, all-mma =================
// grid (T/16, n_equi, B), 512 threads, 1 CTA/SM.
#define OF_HT  0                          // hT[i][r] stride 136 : 17408
#define OF_K   17408                      // k[s][d] stride 132 : 8448
#define OF_V   (OF_K + 8448)              // v[s][d] stride 136 : 8704
#define OF_AT  (OF_V + 8704)              // AT[i][m] stride 24 : 3072
#define OF_Q   (OF_AT + 3072)             // Q[m][o] stride 132 : 2112
#define OF_U   (OF_Q + 2112)              // U[m][*] stride 132 : 2112
#define K2_SMEM_F (OF_U + 2112)           // 41856 floats = 167424 bytes

__global__ __launch_bounds__(512, 1)
void fused_kernel(const float* __restrict__ h_prime,
                  const float* __restrict__ bq,
                  const float* __restrict__ bg,
                  const float* __restrict__ bb,
                  float* __restrict__ out) {
    extern __shared__ float sm[];
    float* hT  = sm + OF_HT;   // [i*136 + g*16+m]
    float* ksm = sm + OF_K;    // [s*132 + d]
    float* vsm = sm + OF_V;    // [s*136 + d]
    float* AT  = sm + OF_AT;   // [k*24 + m]  (inv feat -> ctx)
    float* Q   = sm + OF_Q;    // [m*132 + o] (q -> gamma)
    float* U   = sm + OF_U;    // [m*132 + *] (scores -> beta)

    const int tid = threadIdx.x;
    const int wid = tid >> 5;
    const int l   = tid & 31;
    const int lr  = l >> 2;     // 0..7
    const int lc  = l & 3;      // 0..3
    const int t0  = blockIdx.x * TOK;
    const int n   = blockIdx.y;
    const int b   = blockIdx.z;
    const long long base = ((long long)(b * NE + n) * TT + t0) * DD;

    // ---- phase A: loads ----
#pragma unroll
    for (int k = 0; k < 8; k++) {
        int e = tid + k * 512;                 // 4096 float4
        int m = e & 15, d4 = e >> 4;
        int d = d4 * 4, g = d >> 7, i0 = d & 127;
        float4 hv = *reinterpret_cast<const float4*>(&h_prime[base + m * DD + d]);
        int r = g * 16 + m;
        hT[(i0 + 0) * 136 + r] = hv.x;
        hT[(i0 + 1) * 136 + r] = hv.y;
        hT[(i0 + 2) * 136 + r] = hv.z;
        hT[(i0 + 3) * 136 + r] = hv.w;
    }
#pragma unroll
    for (int k = 0; k < 4; k++) {
        int e = tid + k * 512;                 // 2048 float4
        int s = e >> 5, d4 = e & 31;
        *reinterpret_cast<float4*>(&ksm[s * 132 + d4 * 4]) =
            *reinterpret_cast<const float4*>(&g_k[(b * SS + s) * BL + d4 * 4]);
        *reinterpret_cast<float4*>(&vsm[s * 136 + d4 * 4]) =
            *reinterpret_cast<const float4*>(&g_v[(b * SS + s) * BL + d4 * 4]);
    }
    __syncthreads();

    // ---- phase B: group max -> AT[i][m] (stride 24) ----
#pragma unroll
    for (int k = 0; k < 4; k++) {
        int idx = tid + k * 512;               // 2048
        int i = idx >> 4, m = idx & 15;
        const float* row = &hT[i * 136 + m];
        float mx = row[0];
#pragma unroll
        for (int g = 1; g < GG; g++) mx = fmaxf(mx, row[g * 16]);
        AT[i * 24 + m] = mx;
    }
    __syncthreads();

    // ---- phase C: q = inv @ WqT + bq (mma, frag weights) -> Q[m][o] ----
    {
        const int o8 = wid * 8;
        float d[4] = {0.f, 0.f, 0.f, 0.f};
#pragma unroll 4
        for (int kk = 0; kk < 16; kk++) {
            const int i0 = kk * 8;
            uint32_t a[4], bf[2];
            a[0] = f2tf32(AT[(i0 + lc) * 24 + lr]);
            a[1] = f2tf32(AT[(i0 + lc) * 24 + lr + 8]);
            a[2] = f2tf32(AT[(i0 + lc + 4) * 24 + lr]);
            a[3] = f2tf32(AT[(i0 + lc + 4) * 24 + lr + 8]);
            uint2 w2 = g_wqf[(wid * 16 + kk) * 32 + l];
            bf[0] = w2.x; bf[1] = w2.y;
            mma_tf32(d, a, bf);
        }
        float2 bv2 = *reinterpret_cast<const float2*>(&bq[o8 + lc * 2]);
        Q[lr * 132 + o8 + lc * 2]           = d[0] + bv2.x;
        Q[lr * 132 + o8 + lc * 2 + 1]       = d[1] + bv2.y;
        Q[(lr + 8) * 132 + o8 + lc * 2]     = d[2] + bv2.x;
        Q[(lr + 8) * 132 + o8 + lc * 2 + 1] = d[3] + bv2.y;
    }
    __syncthreads();

    // ---- phase D: scores = q.k * SCALE (mma, 8 warps) -> U[m][s] ----
    if (wid < 8) {
        const int s8 = wid * 8;
        float d[4] = {0.f, 0.f, 0.f, 0.f};
#pragma unroll 4
        for (int kk = 0; kk < 16; kk++) {
            const int i0 = kk * 8;
            uint32_t a[4], bf[2];
            a[0] = f2tf32(Q[lr * 132 + i0 + lc]);
            a[1] = f2tf32(Q[(lr + 8) * 132 + i0 + lc]);
            a[2] = f2tf32(Q[lr * 132 + i0 + lc + 4]);
            a[3] = f2tf32(Q[(lr + 8) * 132 + i0 + lc + 4]);
            bf[0] = f2tf32(ksm[(s8 + lr) * 132 + i0 + lc]);
            bf[1] = f2tf32(ksm[(s8 + lr) * 132 + i0 + lc + 4]);
            mma_tf32(d, a, bf);
        }
        U[lr * 132 + s8 + lc * 2]           = d[0] * SCALE;
        U[lr * 132 + s8 + lc * 2 + 1]       = d[1] * SCALE;
        U[(lr + 8) * 132 + s8 + lc * 2]     = d[2] * SCALE;
        U[(lr + 8) * 132 + s8 + lc * 2 + 1] = d[3] * SCALE;
    }
    __syncthreads();

    // ---- phase E: softmax, one warp per row ----
    {
        float x0 = U[wid * 132 + l];
        float x1 = U[wid * 132 + l + 32];
        float mx = fmaxf(x0, x1);
#pragma unroll
        for (int off = 16; off > 0; off >>= 1)
            mx = fmaxf(mx, __shfl_xor_sync(0xffffffffu, mx, off));
        float e0 = __expf(x0 - mx), e1 = __expf(x1 - mx);
        float s = e0 + e1;
#pragma unroll
        for (int off = 16; off > 0; off >>= 1)
            s += __shfl_xor_sync(0xffffffffu, s, off);
        float inv = 1.f / s;
        U[wid * 132 + l]      = e0 * inv;
        U[wid * 132 + l + 32] = e1 * inv;
    }
    __syncthreads();

    // ---- phase F: ctx = attn @ v (mma) -> AT[d][m] (stride 24) ----
    {
        const int o8 = wid * 8;
        float d[4] = {0.f, 0.f, 0.f, 0.f};
#pragma unroll 4
        for (int kk = 0; kk < 8; kk++) {
            const int i0 = kk * 8;
            uint32_t a[4], bf[2];
            a[0] = f2tf32(U[lr * 132 + i0 + lc]);
            a[1] = f2tf32(U[(lr + 8) * 132 + i0 + lc]);
            a[2] = f2tf32(U[lr * 132 + i0 + lc + 4]);
            a[3] = f2tf32(U[(lr + 8) * 132 + i0 + lc + 4]);
            bf[0] = f2tf32(vsm[(i0 + lc) * 136 + o8 + lr]);
            bf[1] = f2tf32(vsm[(i0 + lc + 4) * 136 + o8 + lr]);
            mma_tf32(d, a, bf);
        }
        AT[(o8 + lc * 2) * 24 + lr]         = d[0];
        AT[(o8 + lc * 2 + 1) * 24 + lr]     = d[1];
        AT[(o8 + lc * 2) * 24 + lr + 8]     = d[2];
        AT[(o8 + lc * 2 + 1) * 24 + lr + 8] = d[3];
    }
    __syncthreads();

    // ---- phase G: gamma & beta (merged mma, frag weights) ----
    {
        const int o8 = wid * 8;
        float dg[4] = {0.f, 0.f, 0.f, 0.f};
        float db[4] = {0.f, 0.f, 0.f, 0.f};
#pragma unroll 4
        for (int kk = 0; kk < 16; kk++) {
            const int i0 = kk * 8;
            uint32_t a[4], bG[2], bB[2];
            a[0] = f2tf32(AT[(i0 + lc) * 24 + lr]);
            a[1] = f2tf32(AT[(i0 + lc) * 24 + lr + 8]);
            a[2] = f2tf32(AT[(i0 + lc + 4) * 24 + lr]);
            a[3] = f2tf32(AT[(i0 + lc + 4) * 24 + lr + 8]);
            uint2 wg2 = g_wgf[(wid * 16 + kk) * 32 + l];
            uint2 wb2 = g_wbf[(wid * 16 + kk) * 32 + l];
            bG[0] = wg2.x; bG[1] = wg2.y;
            bB[0] = wb2.x; bB[1] = wb2.y;
            mma_tf32(dg, a, bG);
            mma_tf32(db, a, bB);
        }
        float2 bgv = *reinterpret_cast<const float2*>(&bg[o8 + lc * 2]);
        float2 bbv = *reinterpret_cast<const float2*>(&bb[o8 + lc * 2]);
        Q[lr * 132 + o8 + lc * 2]           = dg[0] + bgv.x;
        Q[lr * 132 + o8 + lc * 2 + 1]       = dg[1] + bgv.y;
        Q[(lr + 8) * 132 + o8 + lc * 2]     = dg[2] + bgv.x;
        Q[(lr + 8) * 132 + o8 + lc * 2 + 1] = dg[3] + bgv.y;
        U[lr * 132 + o8 + lc * 2]           = db[0] + bbv.x;
        U[lr * 132 + o8 + lc * 2 + 1]       = db[1] + bbv.y;
        U[(lr + 8) * 132 + o8 + lc * 2]     = db[2] + bbv.x;
        U[(lr + 8) * 132 + o8 + lc * 2 + 1] = db[3] + bbv.y;
    }
    __syncthreads();

    // ---- phase J: equi GEMM (mma, frag We) + epilogue ----
    {
        const int r0 = (wid >> 2) * 32;      // 32-row warp tile
        const int oc = wid & 3;              // 32-col warp tile
        const int o0 = oc * 32;

        float d[2][4][4];
#pragma unroll
        for (int mt = 0; mt < 2; mt++)
#pragma unroll
            for (int nt = 0; nt < 4; nt++)
#pragma unroll
                for (int j = 0; j < 4; j++) d[mt][nt][j] = 0.f;

#pragma unroll 2
        for (int k = 0; k < 16; k++) {
            const int i0 = k * 8;
            uint32_t a[2][4], bfr[4][2];
#pragma unroll
            for (int mt = 0; mt < 2; mt++) {
                const int rb = r0 + mt * 16 + lr;
                a[mt][0] = f2tf32(hT[(i0 + lc) * 136 + rb]);
                a[mt][1] = f2tf32(hT[(i0 + lc) * 136 + rb + 8]);
                a[mt][2] = f2tf32(hT[(i0 + lc + 4) * 136 + rb]);
                a[mt][3] = f2tf32(hT[(i0 + lc + 4) * 136 + rb + 8]);
            }
            uint4 b01 = g_wef[((oc * 16 + k) * 2 + 0) * 32 + l];
            uint4 b23 = g_wef[((oc * 16 + k) * 2 + 1) * 32 + l];
            bfr[0][0] = b01.x; bfr[0][1] = b01.y;
            bfr[1][0] = b01.z; bfr[1][1] = b01.w;
            bfr[2][0] = b23.x; bfr[2][1] = b23.y;
            bfr[3][0] = b23.z; bfr[3][1] = b23.w;
#pragma unroll
            for (int mt = 0; mt < 2; mt++)
#pragma unroll
                for (int nt = 0; nt < 4; nt++)
                    mma_tf32(d[mt][nt], a[mt], bfr[nt]);
        }

        // epilogue from C fragments
#pragma unroll
        for (int mt = 0; mt < 2; mt++) {
#pragma unroll
            for (int rh = 0; rh < 2; rh++) {
                const int r = r0 + mt * 16 + lr + rh * 8;
                const int m = r & 15, g = r >> 4;
                float* orow = out + base + m * DD + g * 128;
#pragma unroll
                for (int nt = 0; nt < 4; nt++) {
                    const int o = o0 + nt * 8 + lc * 2;
                    float e0 = d[mt][nt][rh * 2 + 0];
                    float e1 = d[mt][nt][rh * 2 + 1];
                    float2 gam = *reinterpret_cast<const float2*>(&Q[m * 132 + o]);
                    float2 bet = *reinterpret_cast<const float2*>(&U[m * 132 + o]);
                    float c0 = AT[(o + 0) * 24 + m];
                    float c1 = AT[(o + 1) * 24 + m];
                    float res0 = hT[(o + 0) * 136 + r];
                    float res1 = hT[(o + 1) * 136 + r];
                    float g0 = 1.f / (1.f + __expf(-c0));
                    float g1 = 1.f / (1.f + __expf(-c1));
                    float2 ov;
                    ov.x = res0 + g0 * (gam.x * e0 + bet.x);
                    ov.y = res1 + g1 * (gam.y * e1 + bet.y);
                    *reinterpret_cast<float2*>(&orow[o]) = ov;
                }
            }
        }
    }
}

// ================= launcher =================
extern "C" void kernel_launch(void* const* d_in, const int* in_sizes, int n_in,
                              void* d_out, int out_size) {
    const float* h_prime = (const float*)d_in[0];
    const float* h_llm   = (const float*)d_in[1];
    const float* Wq = (const float*)d_in[2];
    const float* bq = (const float*)d_in[3];
    const float* Wk = (const float*)d_in[4];
    const float* bk = (const float*)d_in[5];
    const float* Wv = (const float*)d_in[6];
    const float* bv = (const float*)d_in[7];
    const float* Wg = (const float*)d_in[8];
    const float* bg = (const float*)d_in[9];
    const float* Wb = (const float*)d_in[10];
    const float* bb = (const float*)d_in[11];
    const float* We = (const float*)d_in[12];
    float* out = (float*)d_out;

    (void)in_sizes; (void)n_in; (void)out_size;

    size_t sm1 = K1_SMEM_F * sizeof(float);
    size_t sm2 = K2_SMEM_F * sizeof(float);
    cudaFuncSetAttribute(kv_partial_kernel,
                         cudaFuncAttributeMaxDynamicSharedMemorySize, (int)sm1);
    cudaFuncSetAttribute(fused_kernel,
                         cudaFuncAttributeMaxDynamicSharedMemorySize, (int)sm2);

    frag_prep_kernel<<<48, 256>>>(Wq, Wg, Wb, We);
    kv_partial_kernel<<<dim3(16, BB), 512, sm1>>>(h_llm, Wk, Wv);
    kv_reduce_kernel<<<(BB * SS * BL) / 256, 256>>>(bk, bv);
    fused_kernel<<<dim3(TT / TOK, NE, BB), 512, sm2>>>(
        h_prime, bq, bg, bb, out);
}

// round 10
// speedup vs baseline: 4.3410x; 1.1106x over previous
#include <cuda_runtime.h>
#include <math.h>
#include <cstdint>

// ---------------- problem constants ----------------
#define BB     8      // batch
#define NE     4      // n_equi
#define TT     1024   // T
#define DD     1024   // D_eq
#define GG     8      // N_GROUP
#define BL     128    // BLOCKS
#define SS     64     // T_text
#define DL     2048   // d_llm
#define SCALE  0.08838834764831843f   // 128^-0.5

#define TOK    16     // tokens per block in fused kernel
#define NCH    32     // kv split chunks
#define KC     64     // d_llm per chunk

// ---------------- scratch (device globals; no allocs allowed) ----------------
__device__ float g_kp[NCH * BB * SS * BL];
__device__ float g_vp[NCH * BB * SS * BL];
__device__ float g_k [BB * SS * BL];
__device__ float g_v [BB * SS * BL];

// fragment-ordered weights (pre-tf32). wq/wg/wb: [wid 16][kk 16][lane 32]
// we: [oc 4][k 16][ntp 2][lane 32] (uint4 packs 2 n-tiles)
__device__ uint2 g_wqf[16 * 16 * 32];
__device__ uint2 g_wgf[16 * 16 * 32];
__device__ uint2 g_wbf[16 * 16 * 32];
__device__ uint4 g_wef[4 * 16 * 2 * 32];

__device__ __forceinline__ uint32_t f2tf32(float x) {
    uint32_t r; asm("cvt.rna.tf32.f32 %0, %1;" : "=r"(r) : "f"(x)); return r;
}

__device__ __forceinline__ void mma_tf32(float d[4], const uint32_t a[4],
                                         const uint32_t b[2]) {
    asm volatile(
        "mma.sync.aligned.m16n8k8.row.col.f32.tf32.tf32.f32 "
        "{%0,%1,%2,%3}, {%4,%5,%6,%7}, {%8,%9}, {%0,%1,%2,%3};"
        : "+f"(d[0]), "+f"(d[1]), "+f"(d[2]), "+f"(d[3])
        : "r"(a[0]), "r"(a[1]), "r"(a[2]), "r"(a[3]),
          "r"(b[0]), "r"(b[1]));
}

// ================= kernel 0: fragment prep =================
__global__ void frag_prep_kernel(const float* __restrict__ Wq,
                                 const float* __restrict__ Wg,
                                 const float* __restrict__ Wb,
                                 const float* __restrict__ We) {
    int idx = blockIdx.x * 256 + threadIdx.x;
    if (idx < 8192) {
        int lane = idx & 31, kk = (idx >> 5) & 15, w = idx >> 9;
        int lr = lane >> 2, lc = lane & 3;
        int ofs = (w * 8 + lr) * 128 + kk * 8 + lc;
        g_wqf[idx] = make_uint2(f2tf32(Wq[ofs]), f2tf32(Wq[ofs + 4]));
        g_wgf[idx] = make_uint2(f2tf32(Wg[ofs]), f2tf32(Wg[ofs + 4]));
        g_wbf[idx] = make_uint2(f2tf32(Wb[ofs]), f2tf32(Wb[ofs + 4]));
    } else if (idx < 8192 + 4096) {
        int j = idx - 8192;
        int lane = j & 31, ntp = (j >> 5) & 1, k = (j >> 6) & 15, oc = j >> 10;
        int lr = lane >> 2, lc = lane & 3;
        int r0 = (oc * 32 + ntp * 16 + lr) * 128 + k * 8 + lc;
        int r1 = r0 + 8 * 128;
        g_wef[j] = make_uint4(f2tf32(We[r0]), f2tf32(We[r0 + 4]),
                              f2tf32(We[r1]), f2tf32(We[r1 + 4]));
    }
}

// ================= kernel 1: k/v projection, 32 chunks, 2 CTA/SM =========
#define K1_SMEM_F (SS * KC + 2 * KC * 129)
__global__ __launch_bounds__(512, 2)
void kv_partial_kernel(const float* __restrict__ h_llm,
                       const float* __restrict__ Wk,
                       const float* __restrict__ Wv) {
    extern __shared__ float sm[];
    float* hs  = sm;                 // [s][d]  64*64
    float* wkT = sm + SS * KC;       // [d][o]  stride 129
    float* wvT = wkT + KC * 129;

    const int dc  = blockIdx.x;
    const int b   = blockIdx.y;
    const int tid = threadIdx.x;

    for (int e = tid; e < SS * (KC / 4); e += 512) {        // 1024 float4
        int s = e >> 4, d4 = e & 15;
        *reinterpret_cast<float4*>(&hs[s * KC + d4 * 4]) =
            *reinterpret_cast<const float4*>(&h_llm[(b * SS + s) * DL + dc * KC + d4 * 4]);
    }
    for (int e = tid; e < BL * (KC / 4); e += 512) {        // 2048 float4
        int d4 = e & 15, o = e >> 4;
        float4 wk = *reinterpret_cast<const float4*>(&Wk[o * DL + dc * KC + d4 * 4]);
        float4 wv = *reinterpret_cast<const float4*>(&Wv[o * DL + dc * KC + d4 * 4]);
        int d0 = d4 * 4;
        wkT[(d0 + 0) * 129 + o] = wk.x; wkT[(d0 + 1) * 129 + o] = wk.y;
        wkT[(d0 + 2) * 129 + o] = wk.z; wkT[(d0 + 3) * 129 + o] = wk.w;
        wvT[(d0 + 0) * 129 + o] = wv.x; wvT[(d0 + 1) * 129 + o] = wv.y;
        wvT[(d0 + 2) * 129 + o] = wv.z; wvT[(d0 + 3) * 129 + o] = wv.w;
    }
    __syncthreads();

    const int o = tid & 127, qi = tid >> 7;
    for (int st = 0; st < 4; st++) {
        int s0 = qi * 16 + st * 4;
        float ak[4] = {0.f, 0.f, 0.f, 0.f};
        float av[4] = {0.f, 0.f, 0.f, 0.f};
#pragma unroll 4
        for (int d4 = 0; d4 < KC / 4; d4++) {
            float4 h0 = *reinterpret_cast<const float4*>(&hs[(s0 + 0) * KC + d4 * 4]);
            float4 h1 = *reinterpret_cast<const float4*>(&hs[(s0 + 1) * KC + d4 * 4]);
            float4 h2 = *reinterpret_cast<const float4*>(&hs[(s0 + 2) * KC + d4 * 4]);
            float4 h3 = *reinterpret_cast<const float4*>(&hs[(s0 + 3) * KC + d4 * 4]);
            const float hh[4][4] = {{h0.x, h0.y, h0.z, h0.w},
                                    {h1.x, h1.y, h1.z, h1.w},
                                    {h2.x, h2.y, h2.z, h2.w},
                                    {h3.x, h3.y, h3.z, h3.w}};
#pragma unroll
            for (int jd = 0; jd < 4; jd++) {
                float wk = wkT[(d4 * 4 + jd) * 129 + o];
                float wv = wvT[(d4 * 4 + jd) * 129 + o];
#pragma unroll
                for (int j = 0; j < 4; j++) {
                    ak[j] = fmaf(hh[j][jd], wk, ak[j]);
                    av[j] = fmaf(hh[j][jd], wv, av[j]);
                }
            }
        }
#pragma unroll
        for (int j = 0; j < 4; j++) {
            int oidx = ((dc * BB + b) * SS + s0 + j) * BL + o;
            g_kp[oidx] = ak[j];
            g_vp[oidx] = av[j];
        }
    }
}

// ================= kernel 1b: reduce partials + bias =================
__global__ void kv_reduce_kernel(const float* __restrict__ bk,
                                 const float* __restrict__ bv) {
    int idx = blockIdx.x * 256 + threadIdx.x;
    int o = idx & 127;
    float sk = bk[o], sv = bv[o];
#pragma unroll
    for (int dc = 0; dc < NCH; dc++) {
        sk += g_kp[dc * (BB * SS * BL) + idx];
        sv += g_vp[dc * (BB * SS * BL) + idx];
    }
    g_k[idx] = sk;
    g_v[idx] = sv;
}

// ================= kernel 2: fused, all-mma =================
// grid (T/16, n_equi, B), 512 threads, 1 CTA/SM.
#define HS     1036                       // H row stride (1036 mod 32 == 12)
#define OF_H   0                          // H[m][d] : 16*1036 = 16576
#define OF_K   16576                      // k[s][d] stride 132 : 8448 (tf32 bits)
#define OF_V   (OF_K + 8448)              // v[s][d] stride 136 : 8704 (tf32 bits)
#define OF_AT  (OF_V + 8704)              // AT[i][m] stride 24 : 3072 (tf32 bits)
#define OF_Q   (OF_AT + 3072)             // Q[m][o] stride 132 : 2112
#define OF_U   (OF_Q + 2112)              // U[m][*] stride 132 : 2112
#define OF_CT  (OF_U + 2112)              // CT gate[m][o] stride 132 : 2112
#define K2_SMEM_F (OF_CT + 2112)          // 43136 floats = 172544 bytes

__global__ __launch_bounds__(512, 1)
void fused_kernel(const float* __restrict__ h_prime,
                  const float* __restrict__ bq,
                  const float* __restrict__ bg,
                  const float* __restrict__ bb,
                  float* __restrict__ out) {
    extern __shared__ float sm[];
    float* H   = sm + OF_H;    // [m*1036 + d] fp32
    float* ksm = sm + OF_K;    // [s*132 + d] tf32 bits
    float* vsm = sm + OF_V;    // [s*136 + d] tf32 bits
    float* AT  = sm + OF_AT;   // [k*24 + m]  tf32 bits (inv feat -> ctx)
    float* Q   = sm + OF_Q;    // [m*132 + o] (q tf32 -> gamma fp32)
    float* U   = sm + OF_U;    // [m*132 + *] (scores fp32 -> probs tf32 -> beta fp32)
    float* CT  = sm + OF_CT;   // [m*132 + o] gate fp32

    const int tid = threadIdx.x;
    const int wid = tid >> 5;
    const int l   = tid & 31;
    const int lr  = l >> 2;     // 0..7
    const int lc  = l & 3;      // 0..3
    const int t0  = blockIdx.x * TOK;
    const int n   = blockIdx.y;
    const int b   = blockIdx.z;
    const long long base = ((long long)(b * NE + n) * TT + t0) * DD;

    // ---- phase A: loads ----
    // h tile: straight row-major copy, coalesced float4
#pragma unroll
    for (int k = 0; k < 8; k++) {
        int e = tid + k * 512;                 // 4096 float4
        int m = e >> 8, c4 = e & 255;
        *reinterpret_cast<float4*>(&H[m * HS + c4 * 4]) =
            *reinterpret_cast<const float4*>(&h_prime[base + m * DD + c4 * 4]);
    }
    // k/v: pre-convert to tf32 bit patterns at staging
#pragma unroll
    for (int k = 0; k < 4; k++) {
        int e = tid + k * 512;                 // 2048 float4
        int s = e >> 5, d4 = e & 31;
        float4 kv4 = *reinterpret_cast<const float4*>(&g_k[(b * SS + s) * BL + d4 * 4]);
        float4 vv4 = *reinterpret_cast<const float4*>(&g_v[(b * SS + s) * BL + d4 * 4]);
        float4 kt, vt;
        kt.x = __uint_as_float(f2tf32(kv4.x)); kt.y = __uint_as_float(f2tf32(kv4.y));
        kt.z = __uint_as_float(f2tf32(kv4.z)); kt.w = __uint_as_float(f2tf32(kv4.w));
        vt.x = __uint_as_float(f2tf32(vv4.x)); vt.y = __uint_as_float(f2tf32(vv4.y));
        vt.z = __uint_as_float(f2tf32(vv4.z)); vt.w = __uint_as_float(f2tf32(vv4.w));
        *reinterpret_cast<float4*>(&ksm[s * 132 + d4 * 4]) = kt;
        *reinterpret_cast<float4*>(&vsm[s * 136 + d4 * 4]) = vt;
    }
    __syncthreads();

    // ---- phase B: group max -> AT[i][m] (tf32 bits), float2 reads ----
#pragma unroll
    for (int k = 0; k < 2; k++) {
        int idx = tid + k * 512;               // 1024 (each handles 2 i)
        int m = idx & 15, i0 = (idx >> 4) * 2;
        float2 mx = *reinterpret_cast<const float2*>(&H[m * HS + i0]);
#pragma unroll
        for (int g = 1; g < GG; g++) {
            float2 v2 = *reinterpret_cast<const float2*>(&H[m * HS + g * 128 + i0]);
            mx.x = fmaxf(mx.x, v2.x);
            mx.y = fmaxf(mx.y, v2.y);
        }
        AT[(i0 + 0) * 24 + m] = __uint_as_float(f2tf32(mx.x));
        AT[(i0 + 1) * 24 + m] = __uint_as_float(f2tf32(mx.y));
    }
    __syncthreads();

    // ---- phase C: q = inv @ WqT + bq (mma) -> Q[m][o] (tf32 bits) ----
    {
        const int o8 = wid * 8;
        float d[4] = {0.f, 0.f, 0.f, 0.f};
#pragma unroll 4
        for (int kk = 0; kk < 16; kk++) {
            const int i0 = kk * 8;
            uint32_t a[4], bf[2];
            a[0] = __float_as_uint(AT[(i0 + lc) * 24 + lr]);
            a[1] = __float_as_uint(AT[(i0 + lc) * 24 + lr + 8]);
            a[2] = __float_as_uint(AT[(i0 + lc + 4) * 24 + lr]);
            a[3] = __float_as_uint(AT[(i0 + lc + 4) * 24 + lr + 8]);
            uint2 w2 = g_wqf[(wid * 16 + kk) * 32 + l];
            bf[0] = w2.x; bf[1] = w2.y;
            mma_tf32(d, a, bf);
        }
        float2 bv2 = *reinterpret_cast<const float2*>(&bq[o8 + lc * 2]);
        Q[lr * 132 + o8 + lc * 2]           = __uint_as_float(f2tf32(d[0] + bv2.x));
        Q[lr * 132 + o8 + lc * 2 + 1]       = __uint_as_float(f2tf32(d[1] + bv2.y));
        Q[(lr + 8) * 132 + o8 + lc * 2]     = __uint_as_float(f2tf32(d[2] + bv2.x));
        Q[(lr + 8) * 132 + o8 + lc * 2 + 1] = __uint_as_float(f2tf32(d[3] + bv2.y));
    }
    __syncthreads();

    // ---- phase D: scores = q.k * SCALE (mma, 8 warps) -> U[m][s] fp32 ----
    if (wid < 8) {
        const int s8 = wid * 8;
        float d[4] = {0.f, 0.f, 0.f, 0.f};
#pragma unroll 4
        for (int kk = 0; kk < 16; kk++) {
            const int i0 = kk * 8;
            uint32_t a[4], bf[2];
            a[0] = __float_as_uint(Q[lr * 132 + i0 + lc]);
            a[1] = __float_as_uint(Q[(lr + 8) * 132 + i0 + lc]);
            a[2] = __float_as_uint(Q[lr * 132 + i0 + lc + 4]);
            a[3] = __float_as_uint(Q[(lr + 8) * 132 + i0 + lc + 4]);
            bf[0] = __float_as_uint(ksm[(s8 + lr) * 132 + i0 + lc]);
            bf[1] = __float_as_uint(ksm[(s8 + lr) * 132 + i0 + lc + 4]);
            mma_tf32(d, a, bf);
        }
        U[lr * 132 + s8 + lc * 2]           = d[0] * SCALE;
        U[lr * 132 + s8 + lc * 2 + 1]       = d[1] * SCALE;
        U[(lr + 8) * 132 + s8 + lc * 2]     = d[2] * SCALE;
        U[(lr + 8) * 132 + s8 + lc * 2 + 1] = d[3] * SCALE;
    }
    __syncthreads();

    // ---- phase E: softmax, one warp per row -> U probs (tf32 bits) ----
    {
        float x0 = U[wid * 132 + l];
        float x1 = U[wid * 132 + l + 32];
        float mx = fmaxf(x0, x1);
#pragma unroll
        for (int off = 16; off > 0; off >>= 1)
            mx = fmaxf(mx, __shfl_xor_sync(0xffffffffu, mx, off));
        float e0 = __expf(x0 - mx), e1 = __expf(x1 - mx);
        float s = e0 + e1;
#pragma unroll
        for (int off = 16; off > 0; off >>= 1)
            s += __shfl_xor_sync(0xffffffffu, s, off);
        float inv = 1.f / s;
        U[wid * 132 + l]      = __uint_as_float(f2tf32(e0 * inv));
        U[wid * 132 + l + 32] = __uint_as_float(f2tf32(e1 * inv));
    }
    __syncthreads();

    // ---- phase F: ctx = attn @ v (mma) -> AT tf32 (for G), CT gate fp32 ----
    {
        const int o8 = wid * 8;
        float d[4] = {0.f, 0.f, 0.f, 0.f};
#pragma unroll 4
        for (int kk = 0; kk < 8; kk++) {
            const int i0 = kk * 8;
            uint32_t a[4], bf[2];
            a[0] = __float_as_uint(U[lr * 132 + i0 + lc]);
            a[1] = __float_as_uint(U[(lr + 8) * 132 + i0 + lc]);
            a[2] = __float_as_uint(U[lr * 132 + i0 + lc + 4]);
            a[3] = __float_as_uint(U[(lr + 8) * 132 + i0 + lc + 4]);
            bf[0] = __float_as_uint(vsm[(i0 + lc) * 136 + o8 + lr]);
            bf[1] = __float_as_uint(vsm[(i0 + lc + 4) * 136 + o8 + lr]);
            mma_tf32(d, a, bf);
        }
        AT[(o8 + lc * 2) * 24 + lr]         = __uint_as_float(f2tf32(d[0]));
        AT[(o8 + lc * 2 + 1) * 24 + lr]     = __uint_as_float(f2tf32(d[1]));
        AT[(o8 + lc * 2) * 24 + lr + 8]     = __uint_as_float(f2tf32(d[2]));
        AT[(o8 + lc * 2 + 1) * 24 + lr + 8] = __uint_as_float(f2tf32(d[3]));
        CT[lr * 132 + o8 + lc * 2]           = 1.f / (1.f + __expf(-d[0]));
        CT[lr * 132 + o8 + lc * 2 + 1]       = 1.f / (1.f + __expf(-d[1]));
        CT[(lr + 8) * 132 + o8 + lc * 2]     = 1.f / (1.f + __expf(-d[2]));
        CT[(lr + 8) * 132 + o8 + lc * 2 + 1] = 1.f / (1.f + __expf(-d[3]));
    }
    __syncthreads();

    // ---- phase G: gamma & beta (merged mma) -> Q (fp32), U (fp32) ----
    {
        const int o8 = wid * 8;
        float dg[4] = {0.f, 0.f, 0.f, 0.f};
        float db[4] = {0.f, 0.f, 0.f, 0.f};
#pragma unroll 4
        for (int kk = 0; kk < 16; kk++) {
            const int i0 = kk * 8;
            uint32_t a[4], bG[2], bB[2];
            a[0] = __float_as_uint(AT[(i0 + lc) * 24 + lr]);
            a[1] = __float_as_uint(AT[(i0 + lc) * 24 + lr + 8]);
            a[2] = __float_as_uint(AT[(i0 + lc + 4) * 24 + lr]);
            a[3] = __float_as_uint(AT[(i0 + lc + 4) * 24 + lr + 8]);
            uint2 wg2 = g_wgf[(wid * 16 + kk) * 32 + l];
            uint2 wb2 = g_wbf[(wid * 16 + kk) * 32 + l];
            bG[0] = wg2.x; bG[1] = wg2.y;
            bB[0] = wb2.x; bB[1] = wb2.y;
            mma_tf32(dg, a, bG);
            mma_tf32(db, a, bB);
        }
        float2 bgv = *reinterpret_cast<const float2*>(&bg[o8 + lc * 2]);
        float2 bbv = *reinterpret_cast<const float2*>(&bb[o8 + lc * 2]);
        Q[lr * 132 + o8 + lc * 2]           = dg[0] + bgv.x;
        Q[lr * 132 + o8 + lc * 2 + 1]       = dg[1] + bgv.y;
        Q[(lr + 8) * 132 + o8 + lc * 2]     = dg[2] + bgv.x;
        Q[(lr + 8) * 132 + o8 + lc * 2 + 1] = dg[3] + bgv.y;
        U[lr * 132 + o8 + lc * 2]           = db[0] + bbv.x;
        U[lr * 132 + o8 + lc * 2 + 1]       = db[1] + bbv.y;
        U[(lr + 8) * 132 + o8 + lc * 2]     = db[2] + bbv.x;
        U[(lr + 8) * 132 + o8 + lc * 2 + 1] = db[3] + bbv.y;
    }
    __syncthreads();

    // ---- phase J: equi GEMM (mma, frag We) + epilogue ----
    {
        const int r0 = (wid >> 2) * 32;      // 32-row warp tile
        const int oc = wid & 3;              // 32-col warp tile
        const int o0 = oc * 32;
        const int g0 = r0 >> 4;

        float d[2][4][4];
#pragma unroll
        for (int mt = 0; mt < 2; mt++)
#pragma unroll
            for (int nt = 0; nt < 4; nt++)
#pragma unroll
                for (int j = 0; j < 4; j++) d[mt][nt][j] = 0.f;

#pragma unroll 2
        for (int k = 0; k < 16; k++) {
            const int i0 = k * 8;
            uint32_t a[2][4], bfr[4][2];
#pragma unroll
            for (int mt = 0; mt < 2; mt++) {
                const float* Alo = &H[lr * HS + (g0 + mt) * 128 + i0 + lc];
                const float* Ahi = &H[(lr + 8) * HS + (g0 + mt) * 128 + i0 + lc];
                a[mt][0] = f2tf32(Alo[0]);
                a[mt][1] = f2tf32(Ahi[0]);
                a[mt][2] = f2tf32(Alo[4]);
                a[mt][3] = f2tf32(Ahi[4]);
            }
            uint4 b01 = g_wef[((oc * 16 + k) * 2 + 0) * 32 + l];
            uint4 b23 = g_wef[((oc * 16 + k) * 2 + 1) * 32 + l];
            bfr[0][0] = b01.x; bfr[0][1] = b01.y;
            bfr[1][0] = b01.z; bfr[1][1] = b01.w;
            bfr[2][0] = b23.x; bfr[2][1] = b23.y;
            bfr[3][0] = b23.z; bfr[3][1] = b23.w;
#pragma unroll
            for (int mt = 0; mt < 2; mt++)
#pragma unroll
                for (int nt = 0; nt < 4; nt++)
                    mma_tf32(d[mt][nt], a[mt], bfr[nt]);
        }

        // epilogue from C fragments (gate/gamma/beta in [m][o] buffers)
#pragma unroll
        for (int mt = 0; mt < 2; mt++) {
#pragma unroll
            for (int rh = 0; rh < 2; rh++) {
                const int m = lr + rh * 8;
                const int g = g0 + mt;
                float* orow = out + base + m * DD + g * 128;
                const float* hrow = &H[m * HS + g * 128];
#pragma unroll
                for (int nt = 0; nt < 4; nt++) {
                    const int o = o0 + nt * 8 + lc * 2;
                    float e0 = d[mt][nt][rh * 2 + 0];
                    float e1 = d[mt][nt][rh * 2 + 1];
                    float2 gam = *reinterpret_cast<const float2*>(&Q[m * 132 + o]);
                    float2 bet = *reinterpret_cast<const float2*>(&U[m * 132 + o]);
                    float2 gat = *reinterpret_cast<const float2*>(&CT[m * 132 + o]);
                    float2 res = *reinterpret_cast<const float2*>(&hrow[o]);
                    float2 ov;
                    ov.x = res.x + gat.x * (gam.x * e0 + bet.x);
                    ov.y = res.y + gat.y * (gam.y * e1 + bet.y);
                    *reinterpret_cast<float2*>(&orow[o]) = ov;
                }
            }
        }
    }
}

// ================= launcher =================
extern "C" void kernel_launch(void* const* d_in, const int* in_sizes, int n_in,
                              void* d_out, int out_size) {
    const float* h_prime = (const float*)d_in[0];
    const float* h_llm   = (const float*)d_in[1];
    const float* Wq = (const float*)d_in[2];
    const float* bq = (const float*)d_in[3];
    const float* Wk = (const float*)d_in[4];
    const float* bk = (const float*)d_in[5];
    const float* Wv = (const float*)d_in[6];
    const float* bv = (const float*)d_in[7];
    const float* Wg = (const float*)d_in[8];
    const float* bg = (const float*)d_in[9];
    const float* Wb = (const float*)d_in[10];
    const float* bb = (const float*)d_in[11];
    const float* We = (const float*)d_in[12];
    float* out = (float*)d_out;

    (void)in_sizes; (void)n_in; (void)out_size;

    size_t sm1 = K1_SMEM_F * sizeof(float);
    size_t sm2 = K2_SMEM_F * sizeof(float);
    cudaFuncSetAttribute(kv_partial_kernel,
                         cudaFuncAttributeMaxDynamicSharedMemorySize, (int)sm1);
    cudaFuncSetAttribute(fused_kernel,
                         cudaFuncAttributeMaxDynamicSharedMemorySize, (int)sm2);

    frag_prep_kernel<<<48, 256>>>(Wq, Wg, Wb, We);
    kv_partial_kernel<<<dim3(NCH, BB), 512, sm1>>>(h_llm, Wk, Wv);
    kv_reduce_kernel<<<(BB * SS * BL) / 256, 256>>>(bk, bv);
    fused_kernel<<<dim3(TT / TOK, NE, BB), 512, sm2>>>(
        h_prime, bq, bg, bb, out);
}